// round 14
// baseline (speedup 1.0000x reference)
#include <cuda_runtime.h>
#include <cuda_fp16.h>

// ---------------------------------------------------------------------------
// DecoderBlock: x:(8,2048,32), H=4, hd=8.
// LN/QKV/post: fp32 f32x2 SIMT. Attention: tensor cores —
// QK^T via mma.m16n8k8.tf32, softmax via ex2.approx.f16x2 (packed MUFU),
// PV via mma.m16n8k16.f16 (fp32 accum); one 128-query tile per block,
// heavy-first ordering, double-buffered K/V staging, one bar.sync per tile.
// ---------------------------------------------------------------------------

constexpr int B_  = 8;
constexpr int T_  = 2048;
constexpr int D_  = 32;
constexpr int BT_ = B_ * T_;

__device__ float g_h[BT_ * D_];   // LN1 output
__device__ float g_q[BT_ * D_];   // (B,H,T,8), pre-scaled by log2e/sqrt(8)
__device__ float g_k[BT_ * D_];
__device__ float g_v[BT_ * D_];
__device__ float g_o[BT_ * D_];   // attention out (B*T,32), normalized

typedef unsigned long long u64;
typedef unsigned int u32;

static __device__ __forceinline__ u64 ffma2(u64 a, u64 b, u64 c) {
    u64 d; asm("fma.rn.f32x2 %0, %1, %2, %3;" : "=l"(d) : "l"(a), "l"(b), "l"(c));
    return d;
}
static __device__ __forceinline__ u64 pack2(float x, float y) {
    u64 d; asm("mov.b64 %0, {%1, %2};" : "=l"(d) : "f"(x), "f"(y));
    return d;
}
static __device__ __forceinline__ float2 unpack2(u64 d) {
    float2 r; asm("mov.b64 {%0, %1}, %2;" : "=f"(r.x), "=f"(r.y) : "l"(d));
    return r;
}
static __device__ __forceinline__ u32 cvt_tf32(float f) {
    u32 u; asm("cvt.rna.tf32.f32 %0, %1;" : "=r"(u) : "f"(f));
    return u;
}
static __device__ __forceinline__ u32 h2u(__half2 h) {
    u32 u; __builtin_memcpy(&u, &h, 4); return u;
}
static __device__ __forceinline__ __half2 u2h(u32 u) {
    __half2 h; __builtin_memcpy(&h, &u, 4); return h;
}
// packed half2 exp2
static __device__ __forceinline__ __half2 hex2(__half2 h) {
    u32 u = h2u(h);
    asm("ex2.approx.f16x2 %0, %0;" : "+r"(u));
    return u2h(u);
}
// causal mask half2 for key pair (k, k+1) vs row r: lo half = key k
static __device__ __forceinline__ __half2 mask2(int k, int r) {
    u32 m = (k + 1 <= r) ? 0x3C003C00u : ((k <= r) ? 0x00003C00u : 0u);
    return u2h(m);
}
// S = Q(16x8) * K^T(8x8), tf32, C zero-init.
static __device__ __forceinline__ void mma_tf32_zero(float* d, const u32* a, const u32* b) {
    asm("mma.sync.aligned.m16n8k8.row.col.f32.tf32.tf32.f32 "
        "{%0,%1,%2,%3}, {%4,%5,%6,%7}, {%8,%9}, {%10,%11,%12,%13};"
        : "=f"(d[0]), "=f"(d[1]), "=f"(d[2]), "=f"(d[3])
        : "r"(a[0]), "r"(a[1]), "r"(a[2]), "r"(a[3]),
          "r"(b[0]), "r"(b[1]),
          "f"(0.f), "f"(0.f), "f"(0.f), "f"(0.f));
}
// O += P(16x16,f16) * V(16x8,f16), fp32 accumulate.
static __device__ __forceinline__ void mma_f16(float* d, const u32* a, const u32* b) {
    asm("mma.sync.aligned.m16n8k16.row.col.f32.f16.f16.f32 "
        "{%0,%1,%2,%3}, {%4,%5,%6,%7}, {%8,%9}, {%0,%1,%2,%3};"
        : "+f"(d[0]), "+f"(d[1]), "+f"(d[2]), "+f"(d[3])
        : "r"(a[0]), "r"(a[1]), "r"(a[2]), "r"(a[3]),
          "r"(b[0]), "r"(b[1]));
}

// ---------------------------------------------------------------------------
// Kernel 1: LN1 + QKV. 32 tokens/block, 128 threads, grid 512. (unchanged)
// ---------------------------------------------------------------------------
__global__ __launch_bounds__(128) void k_ln_qkv(
    const float* __restrict__ x,
    const float* __restrict__ Wq, const float* __restrict__ Wk,
    const float* __restrict__ Wv,
    const float* __restrict__ g1, const float* __restrict__ b1)
{
    __shared__ __align__(16) float sh_h[32][33];
    __shared__ __align__(16) float sh_w[32][96];   // [d][qkv*32 + head*8 + kk]

    const int tid = threadIdx.x;
    const int t0  = blockIdx.x * 32;

    for (int i4 = tid; i4 < 768; i4 += 128) {
        int i = i4 * 4;
        int type = i >> 10, rem = i & 1023;
        int head = rem >> 8, d = (rem >> 3) & 31, kk = rem & 7;
        const float* W = (type == 0) ? Wq : (type == 1) ? Wk : Wv;
        *(float4*)&sh_w[d][type * 32 + head * 8 + kk] = *(const float4*)(W + rem);
    }

    const int tk = tid >> 2, part = tid & 3;
    const int t  = t0 + tk;
    const int c0 = part * 8;
    const float4* xr = (const float4*)(x + t * 32 + c0);
    float4 v0 = xr[0], v1 = xr[1];
    float s  = v0.x + v0.y + v0.z + v0.w + v1.x + v1.y + v1.z + v1.w;
    float ss = v0.x*v0.x + v0.y*v0.y + v0.z*v0.z + v0.w*v0.w
             + v1.x*v1.x + v1.y*v1.y + v1.z*v1.z + v1.w*v1.w;
    s  += __shfl_xor_sync(0xffffffffu, s, 1);
    ss += __shfl_xor_sync(0xffffffffu, ss, 1);
    s  += __shfl_xor_sync(0xffffffffu, s, 2);
    ss += __shfl_xor_sync(0xffffffffu, ss, 2);
    const float mu = s * 0.03125f;
    const float rs = rsqrtf(ss * 0.03125f - mu * mu + 1e-5f);
    float hv[8];
    {
        const float* vv = (const float*)&v0;
        #pragma unroll
        for (int i = 0; i < 4; i++)
            hv[i] = (vv[i] - mu) * rs * __ldg(g1 + c0 + i) + __ldg(b1 + c0 + i);
        const float* vw = (const float*)&v1;
        #pragma unroll
        for (int i = 0; i < 4; i++)
            hv[4 + i] = (vw[i] - mu) * rs * __ldg(g1 + c0 + 4 + i) + __ldg(b1 + c0 + 4 + i);
    }
    #pragma unroll
    for (int i = 0; i < 8; i++) sh_h[tk][c0 + i] = hv[i];
    float4* hr = (float4*)(g_h + t * 32 + c0);
    hr[0] = make_float4(hv[0], hv[1], hv[2], hv[3]);
    hr[1] = make_float4(hv[4], hv[5], hv[6], hv[7]);
    __syncthreads();

    const int to = tid >> 3;
    const int oo = tid & 7;
    u64 acc0[6] = {0,0,0,0,0,0}, acc1[6] = {0,0,0,0,0,0};

    #pragma unroll 4
    for (int kd = 0; kd < 32; kd++) {
        float a0 = sh_h[2 * to][kd];
        float a1 = sh_h[2 * to + 1][kd];
        u64 ap0 = pack2(a0, a0), ap1 = pack2(a1, a1);
        const ulonglong2* wr = (const ulonglong2*)&sh_w[kd][oo * 12];
        ulonglong2 w0 = wr[0], w1 = wr[1], w2 = wr[2];
        u64 wv[6] = {w0.x, w0.y, w1.x, w1.y, w2.x, w2.y};
        #pragma unroll
        for (int i = 0; i < 6; i++) {
            acc0[i] = ffma2(ap0, wv[i], acc0[i]);
            acc1[i] = ffma2(ap1, wv[i], acc1[i]);
        }
    }

    const float QS = 0.51006973f;            // log2(e)/sqrt(8)
    const int b   = t0 >> 11;
    const int ttl = (t0 & 2047) + 2 * to;
    #pragma unroll
    for (int i2 = 0; i2 < 6; i2++) {
        int o    = oo * 12 + 2 * i2;
        int type = o >> 5;
        int head = (o >> 3) & 3;
        int kk   = o & 7;
        float* base = (type == 0) ? g_q : (type == 1) ? g_k : g_v;
        float sc = (type == 0) ? QS : 1.f;
        float2 u0 = unpack2(acc0[i2]);
        float2 u1 = unpack2(acc1[i2]);
        float* p = base + ((b * 4 + head) * 2048 + ttl) * 8 + kk;
        *(float2*)(p)     = make_float2(u0.x * sc, u0.y * sc);
        *(float2*)(p + 8) = make_float2(u1.x * sc, u1.y * sc);
    }
}

// ---------------------------------------------------------------------------
// Kernel 2: causal attention with tensor cores, f16x2 softmax, dbl-buffer.
// grid (32, 16), 256 threads (8 warps). Block (bh, y) handles query tile
// j = 15 - y (heavy blocks first). Warp w owns query rows [16w, 16w+16).
// Loop key tiles kt = 0..j.
// ---------------------------------------------------------------------------
static __device__ __forceinline__ void attn_dchunk(
    const u32* __restrict__ qf, const u32 kb[2][2], const u32* __restrict__ vb,
    float* __restrict__ o, float& l0, float& l1,
    bool diag, int keybase, int r0, int tig2)
{
    float s0[4], s1[4];
    mma_tf32_zero(s0, qf, kb[0]);
    mma_tf32_zero(s1, qf, kb[1]);
    __half2 h0 = hex2(__floats2half2_rn(s0[0], s0[1]));   // row r0,   keys kb0
    __half2 h1 = hex2(__floats2half2_rn(s0[2], s0[3]));   // row r0+8, keys kb0
    __half2 h2 = hex2(__floats2half2_rn(s1[0], s1[1]));   // row r0,   keys kb1
    __half2 h3 = hex2(__floats2half2_rn(s1[2], s1[3]));   // row r0+8, keys kb1
    if (diag) {
        const int k0 = keybase + tig2;
        const int k1 = keybase + 8 + tig2;
        h0 = __hmul2(h0, mask2(k0, r0));
        h1 = __hmul2(h1, mask2(k0, r0 + 8));
        h2 = __hmul2(h2, mask2(k1, r0));
        h3 = __hmul2(h3, mask2(k1, r0 + 8));
    }
    {
        float2 f0 = __half22float2(__hadd2(h0, h2));
        l0 += f0.x + f0.y;
        float2 f1 = __half22float2(__hadd2(h1, h3));
        l1 += f1.x + f1.y;
    }
    u32 a[4] = { h2u(h0), h2u(h1), h2u(h2), h2u(h3) };
    mma_f16(o, a, vb);
}

__global__ __launch_bounds__(256) void k_attn()
{
    __shared__ u32 sK[2][128 * 12];   // tf32 K tiles, row stride 12
    __shared__ u32 sV[2][8 * 68];     // half2 V: [dim][keypair], stride 68

    const int tid = threadIdx.x;
    const int w   = tid >> 5;          // warp 0..7
    const int ln  = tid & 31;
    const int g   = ln >> 2;           // groupID 0..7
    const int tig = ln & 3;            // 0..3
    const int bh  = blockIdx.x;
    const int j   = 15 - (int)blockIdx.y;   // heavy tiles first

    const float* Qg = g_q + bh * T_ * 8;
    const int qa0 = j * 128 + w * 16 + g;

    u32 qaf[4];
    qaf[0] = cvt_tf32(Qg[(qa0)     * 8 + tig]);
    qaf[1] = cvt_tf32(Qg[(qa0 + 8) * 8 + tig]);
    qaf[2] = cvt_tf32(Qg[(qa0)     * 8 + tig + 4]);
    qaf[3] = cvt_tf32(Qg[(qa0 + 8) * 8 + tig + 4]);

    float oa[4] = {0.f, 0.f, 0.f, 0.f};
    float la0 = 0.f, la1 = 0.f;

    const int srow  = tid >> 1;        // staging row 0..127
    const int shalf = tid & 1;
    const float* Kr = g_k + (bh * T_ + srow) * 8 + shalf * 4;
    const float* Vr = g_v + (bh * T_ + srow) * 8 + shalf * 4;

    // prefetch tile 0
    float4 kreg = *(const float4*)(Kr);
    float4 vreg = *(const float4*)(Vr);

    for (int kt = 0; kt <= j; kt++) {
        const int s0 = kt * 128;
        const int buf = kt & 1;

        // ---- write staged registers into smem[buf] ----
        {
            u32* kd = &sK[buf][srow * 12 + shalf * 4];
            kd[0] = cvt_tf32(kreg.x); kd[1] = cvt_tf32(kreg.y);
            kd[2] = cvt_tf32(kreg.z); kd[3] = cvt_tf32(kreg.w);
            float px = __shfl_xor_sync(0xffffffffu, vreg.x, 2);
            float py = __shfl_xor_sync(0xffffffffu, vreg.y, 2);
            float pz = __shfl_xor_sync(0xffffffffu, vreg.z, 2);
            float pw = __shfl_xor_sync(0xffffffffu, vreg.w, 2);
            if ((tid & 2) == 0) {            // even row of the key pair
                int kp = tid >> 2;
                int d0 = shalf * 4;
                sV[buf][(d0 + 0) * 68 + kp] = h2u(__floats2half2_rn(vreg.x, px));
                sV[buf][(d0 + 1) * 68 + kp] = h2u(__floats2half2_rn(vreg.y, py));
                sV[buf][(d0 + 2) * 68 + kp] = h2u(__floats2half2_rn(vreg.z, pz));
                sV[buf][(d0 + 3) * 68 + kp] = h2u(__floats2half2_rn(vreg.w, pw));
            }
        }
        __syncthreads();

        // ---- prefetch next tile (overlaps with compute below) ----
        if (kt < j) {
            kreg = *(const float4*)(Kr + (kt + 1) * 128 * 8);
            vreg = *(const float4*)(Vr + (kt + 1) * 128 * 8);
        }

        const bool dA = (kt == j);

        #pragma unroll 2
        for (int c = 0; c < 8; c++) {
            u32 kb[2][2];
            const u32* k0r = &sK[buf][(16 * c + g) * 12];
            const u32* k1r = &sK[buf][(16 * c + 8 + g) * 12];
            kb[0][0] = k0r[tig]; kb[0][1] = k0r[tig + 4];
            kb[1][0] = k1r[tig]; kb[1][1] = k1r[tig + 4];
            u32 vb[2];
            vb[0] = sV[buf][g * 68 + 8 * c + tig];
            vb[1] = sV[buf][g * 68 + 8 * c + tig + 4];

            attn_dchunk(qaf, kb, vb, oa, la0, la1, dA, s0 + 16 * c, qa0, 2 * tig);
        }
        // single sync per tile: next iteration writes smem[buf^1], whose
        // readers finished before this iteration's sync.
    }

    // ---- finalize: reduce l over the quad, normalize, store ----
    la0 += __shfl_xor_sync(0xffffffffu, la0, 1);
    la0 += __shfl_xor_sync(0xffffffffu, la0, 2);
    la1 += __shfl_xor_sync(0xffffffffu, la1, 1);
    la1 += __shfl_xor_sync(0xffffffffu, la1, 2);
    const float ra0 = __fdividef(1.f, la0);
    const float ra1 = __fdividef(1.f, la1);

    const int bb = bh >> 2, h = bh & 3;
    const int colo = h * 8 + 2 * tig;
    *(float2*)(g_o + (bb * T_ + qa0)     * 32 + colo) = make_float2(oa[0] * ra0, oa[1] * ra0);
    *(float2*)(g_o + (bb * T_ + qa0 + 8) * 32 + colo) = make_float2(oa[2] * ra1, oa[3] * ra1);
}

// ---------------------------------------------------------------------------
// Kernel 3: proj + residual + LN2 + FFN + residual. 32 tokens, 256 threads,
// grid 512. (unchanged)
// ---------------------------------------------------------------------------
constexpr int SM3_FLOATS = 1024 + 4096 + 4096 + 128 + 128 + 32 * 33 + 32 * 129;
constexpr int SM3_BYTES  = SM3_FLOATS * 4;

__global__ __launch_bounds__(256) void k_post(
    float* __restrict__ out,
    const float* __restrict__ Wp, const float* __restrict__ bp,
    const float* __restrict__ W1, const float* __restrict__ b1v,
    const float* __restrict__ W2, const float* __restrict__ b2v,
    const float* __restrict__ g2, const float* __restrict__ bt2)
{
    extern __shared__ float sm[];
    float* sWp  = sm;
    float* sW1  = sWp + 1024;
    float* sW2  = sW1 + 4096;
    float* sB   = sW2 + 4096;
    float* sb1  = sB + 128;
    float* sX   = sb1 + 128;
    float* sHid = sX + 32 * 33;

    const int tid = threadIdx.x;
    const int t0  = blockIdx.x * 32;

    *(float4*)&sWp[tid * 4] = *(const float4*)(Wp + tid * 4);
    for (int i4 = tid; i4 < 1024; i4 += 256)
        *(float4*)&sW1[i4 * 4] = *(const float4*)(W1 + i4 * 4);
    for (int i4 = tid; i4 < 1024; i4 += 256)
        *(float4*)&sW2[i4 * 4] = *(const float4*)(W2 + i4 * 4);
    if (tid < 32) { sB[tid] = bp[tid]; sB[32 + tid] = b2v[tid];
                    sB[64 + tid] = g2[tid]; sB[96 + tid] = bt2[tid]; }
    if (tid >= 128 && tid < 256) sb1[tid - 128] = b1v[tid - 128];

    {
        int row = tid >> 3, c4 = tid & 7;
        float4 v = ((const float4*)(g_o + (t0 + row) * 32))[c4];
        float* d = &sX[row * 33 + c4 * 4];
        d[0] = v.x; d[1] = v.y; d[2] = v.z; d[3] = v.w;
    }
    __syncthreads();

    const int tr = tid >> 3, q8 = tid & 7;
    const int c0 = q8 * 4;
    const int gt = t0 + tr;
    u64 accp[2] = {0, 0};

    #pragma unroll 4
    for (int kd = 0; kd < 32; kd++) {
        float a = sX[tr * 33 + kd];
        u64 ap = pack2(a, a);
        ulonglong2 w0 = *(const ulonglong2*)&sWp[kd * 32 + c0];
        accp[0] = ffma2(ap, w0.x, accp[0]);
        accp[1] = ffma2(ap, w0.y, accp[1]);
    }
    float xv[4];
    {
        float4 h0 = *(const float4*)(g_h + gt * 32 + c0);
        float2 u0 = unpack2(accp[0]), u1 = unpack2(accp[1]);
        xv[0] = h0.x + u0.x + sB[c0 + 0];
        xv[1] = h0.y + u0.y + sB[c0 + 1];
        xv[2] = h0.z + u1.x + sB[c0 + 2];
        xv[3] = h0.w + u1.y + sB[c0 + 3];
    }
    float s = 0.f, ss = 0.f;
    #pragma unroll
    for (int i = 0; i < 4; i++) { s += xv[i]; ss += xv[i] * xv[i]; }
    s  += __shfl_xor_sync(0xffffffffu, s, 1);
    ss += __shfl_xor_sync(0xffffffffu, ss, 1);
    s  += __shfl_xor_sync(0xffffffffu, s, 2);
    ss += __shfl_xor_sync(0xffffffffu, ss, 2);
    s  += __shfl_xor_sync(0xffffffffu, s, 4);
    ss += __shfl_xor_sync(0xffffffffu, ss, 4);
    const float mu = s * 0.03125f;
    const float rs = rsqrtf(ss * 0.03125f - mu * mu + 1e-5f);
    float h2r[4];
    #pragma unroll
    for (int i = 0; i < 4; i++)
        h2r[i] = (xv[i] - mu) * rs * sB[64 + c0 + i] + sB[96 + c0 + i];

    __syncthreads();
    #pragma unroll
    for (int i = 0; i < 4; i++) sX[tr * 33 + c0 + i] = h2r[i];
    __syncthreads();

    const int ttb = tid >> 4;
    const int oo  = tid & 15;
    u64 accB[2][4];
    #pragma unroll
    for (int j = 0; j < 2; j++)
        #pragma unroll
        for (int i = 0; i < 4; i++) accB[j][i] = 0;

    #pragma unroll 4
    for (int k = 0; k < 32; k++) {
        float a0 = sX[(ttb * 2 + 0) * 33 + k];
        float a1 = sX[(ttb * 2 + 1) * 33 + k];
        u64 ap0 = pack2(a0, a0), ap1 = pack2(a1, a1);
        const ulonglong2* wr = (const ulonglong2*)&sW1[k * 128 + oo * 8];
        ulonglong2 ww0 = wr[0], ww1 = wr[1];
        u64 wv[4] = {ww0.x, ww0.y, ww1.x, ww1.y};
        #pragma unroll
        for (int i = 0; i < 4; i++) {
            accB[0][i] = ffma2(ap0, wv[i], accB[0][i]);
            accB[1][i] = ffma2(ap1, wv[i], accB[1][i]);
        }
    }
    #pragma unroll
    for (int j = 0; j < 2; j++)
        #pragma unroll
        for (int i = 0; i < 4; i++) {
            float2 u = unpack2(accB[j][i]);
            float* d = &sHid[(ttb * 2 + j) * 129 + oo * 8 + 2 * i];
            d[0] = fmaxf(u.x + sb1[oo * 8 + 2 * i], 0.f);
            d[1] = fmaxf(u.y + sb1[oo * 8 + 2 * i + 1], 0.f);
        }
    __syncthreads();

    u64 accC[2] = {0, 0};
    #pragma unroll 4
    for (int k = 0; k < 128; k++) {
        float a = sHid[tr * 129 + k];
        u64 ap = pack2(a, a);
        ulonglong2 w0 = *(const ulonglong2*)&sW2[k * 32 + c0];
        accC[0] = ffma2(ap, w0.x, accC[0]);
        accC[1] = ffma2(ap, w0.y, accC[1]);
    }
    float2 u0 = unpack2(accC[0]), u1 = unpack2(accC[1]);
    *(float4*)(out + gt * 32 + c0) = make_float4(
        h2r[0] + u0.x + sB[32 + c0 + 0],
        h2r[1] + u0.y + sB[32 + c0 + 1],
        h2r[2] + u1.x + sB[32 + c0 + 2],
        h2r[3] + u1.y + sB[32 + c0 + 3]);
}

// ---------------------------------------------------------------------------
extern "C" void kernel_launch(void* const* d_in, const int* in_sizes, int n_in,
                              void* d_out, int out_size)
{
    const float* x   = (const float*)d_in[0];
    const float* Wq  = (const float*)d_in[1];
    const float* Wk  = (const float*)d_in[2];
    const float* Wv  = (const float*)d_in[3];
    const float* Wp  = (const float*)d_in[4];
    const float* bp  = (const float*)d_in[5];
    const float* g1  = (const float*)d_in[6];
    const float* b1  = (const float*)d_in[7];
    const float* W1  = (const float*)d_in[8];
    const float* b1f = (const float*)d_in[9];
    const float* W2  = (const float*)d_in[10];
    const float* b2f = (const float*)d_in[11];
    const float* g2  = (const float*)d_in[12];
    const float* bt2 = (const float*)d_in[13];
    float* out = (float*)d_out;

    cudaFuncSetAttribute((const void*)k_post,
                         cudaFuncAttributeMaxDynamicSharedMemorySize, SM3_BYTES);

    k_ln_qkv<<<BT_ / 32, 128>>>(x, Wq, Wk, Wv, g1, b1);

    dim3 ga(B_ * 4, 16);
    k_attn<<<ga, 256>>>();

    k_post<<<BT_ / 32, 256, SM3_BYTES>>>(out, Wp, bp, W1, b1f, W2, b2f, g2, bt2);
}

// round 15
// speedup vs baseline: 1.0288x; 1.0288x over previous
#include <cuda_runtime.h>
#include <cuda_fp16.h>

// ---------------------------------------------------------------------------
// DecoderBlock: x:(8,2048,32), H=4, hd=8.
// LN/QKV/post: fp32 f32x2 SIMT. Attention: tensor cores —
// QK^T via mma.m16n8k8.f16 (f16 operands, fp32 accum), softmax via
// ex2.approx.f16x2, PV via mma.m16n8k16.f16; balanced causal pairing
// (block (bh,j) owns query tiles j and 15-j); double-buffered staging.
// ---------------------------------------------------------------------------

constexpr int B_  = 8;
constexpr int T_  = 2048;
constexpr int D_  = 32;
constexpr int BT_ = B_ * T_;

__device__ float g_h[BT_ * D_];   // LN1 output
__device__ float g_q[BT_ * D_];   // (B,H,T,8), pre-scaled by log2e/sqrt(8)
__device__ float g_k[BT_ * D_];
__device__ float g_v[BT_ * D_];
__device__ float g_o[BT_ * D_];   // attention out (B*T,32), normalized

typedef unsigned long long u64;
typedef unsigned int u32;

static __device__ __forceinline__ u64 ffma2(u64 a, u64 b, u64 c) {
    u64 d; asm("fma.rn.f32x2 %0, %1, %2, %3;" : "=l"(d) : "l"(a), "l"(b), "l"(c));
    return d;
}
static __device__ __forceinline__ u64 pack2(float x, float y) {
    u64 d; asm("mov.b64 %0, {%1, %2};" : "=l"(d) : "f"(x), "f"(y));
    return d;
}
static __device__ __forceinline__ float2 unpack2(u64 d) {
    float2 r; asm("mov.b64 {%0, %1}, %2;" : "=f"(r.x), "=f"(r.y) : "l"(d));
    return r;
}
static __device__ __forceinline__ u32 h2u(__half2 h) {
    u32 u; __builtin_memcpy(&u, &h, 4); return u;
}
static __device__ __forceinline__ __half2 u2h(u32 u) {
    __half2 h; __builtin_memcpy(&h, &u, 4); return h;
}
// packed half2 exp2
static __device__ __forceinline__ __half2 hex2(__half2 h) {
    u32 u = h2u(h);
    asm("ex2.approx.f16x2 %0, %0;" : "+r"(u));
    return u2h(u);
}
// causal mask half2 for key pair (k, k+1) vs row r: lo half = key k
static __device__ __forceinline__ __half2 mask2(int k, int r) {
    u32 m = (k + 1 <= r) ? 0x3C003C00u : ((k <= r) ? 0x00003C00u : 0u);
    return u2h(m);
}
// S = Q(16x8,f16) * K^T(8x8,f16), fp32 out, C zero-init. A: 2 regs, B: 1 reg.
static __device__ __forceinline__ void mma_qk_f16(float* d, const u32* a, u32 b) {
    asm("mma.sync.aligned.m16n8k8.row.col.f32.f16.f16.f32 "
        "{%0,%1,%2,%3}, {%4,%5}, {%6}, {%7,%8,%9,%10};"
        : "=f"(d[0]), "=f"(d[1]), "=f"(d[2]), "=f"(d[3])
        : "r"(a[0]), "r"(a[1]), "r"(b),
          "f"(0.f), "f"(0.f), "f"(0.f), "f"(0.f));
}
// O += P(16x16,f16) * V(16x8,f16), fp32 accumulate.
static __device__ __forceinline__ void mma_f16(float* d, const u32* a, const u32* b) {
    asm("mma.sync.aligned.m16n8k16.row.col.f32.f16.f16.f32 "
        "{%0,%1,%2,%3}, {%4,%5,%6,%7}, {%8,%9}, {%0,%1,%2,%3};"
        : "+f"(d[0]), "+f"(d[1]), "+f"(d[2]), "+f"(d[3])
        : "r"(a[0]), "r"(a[1]), "r"(a[2]), "r"(a[3]),
          "r"(b[0]), "r"(b[1]));
}

// ---------------------------------------------------------------------------
// Kernel 1: LN1 + QKV. 32 tokens/block, 128 threads, grid 512. (unchanged)
// ---------------------------------------------------------------------------
__global__ __launch_bounds__(128) void k_ln_qkv(
    const float* __restrict__ x,
    const float* __restrict__ Wq, const float* __restrict__ Wk,
    const float* __restrict__ Wv,
    const float* __restrict__ g1, const float* __restrict__ b1)
{
    __shared__ __align__(16) float sh_h[32][33];
    __shared__ __align__(16) float sh_w[32][96];   // [d][qkv*32 + head*8 + kk]

    const int tid = threadIdx.x;
    const int t0  = blockIdx.x * 32;

    for (int i4 = tid; i4 < 768; i4 += 128) {
        int i = i4 * 4;
        int type = i >> 10, rem = i & 1023;
        int head = rem >> 8, d = (rem >> 3) & 31, kk = rem & 7;
        const float* W = (type == 0) ? Wq : (type == 1) ? Wk : Wv;
        *(float4*)&sh_w[d][type * 32 + head * 8 + kk] = *(const float4*)(W + rem);
    }

    const int tk = tid >> 2, part = tid & 3;
    const int t  = t0 + tk;
    const int c0 = part * 8;
    const float4* xr = (const float4*)(x + t * 32 + c0);
    float4 v0 = xr[0], v1 = xr[1];
    float s  = v0.x + v0.y + v0.z + v0.w + v1.x + v1.y + v1.z + v1.w;
    float ss = v0.x*v0.x + v0.y*v0.y + v0.z*v0.z + v0.w*v0.w
             + v1.x*v1.x + v1.y*v1.y + v1.z*v1.z + v1.w*v1.w;
    s  += __shfl_xor_sync(0xffffffffu, s, 1);
    ss += __shfl_xor_sync(0xffffffffu, ss, 1);
    s  += __shfl_xor_sync(0xffffffffu, s, 2);
    ss += __shfl_xor_sync(0xffffffffu, ss, 2);
    const float mu = s * 0.03125f;
    const float rs = rsqrtf(ss * 0.03125f - mu * mu + 1e-5f);
    float hv[8];
    {
        const float* vv = (const float*)&v0;
        #pragma unroll
        for (int i = 0; i < 4; i++)
            hv[i] = (vv[i] - mu) * rs * __ldg(g1 + c0 + i) + __ldg(b1 + c0 + i);
        const float* vw = (const float*)&v1;
        #pragma unroll
        for (int i = 0; i < 4; i++)
            hv[4 + i] = (vw[i] - mu) * rs * __ldg(g1 + c0 + 4 + i) + __ldg(b1 + c0 + 4 + i);
    }
    #pragma unroll
    for (int i = 0; i < 8; i++) sh_h[tk][c0 + i] = hv[i];
    float4* hr = (float4*)(g_h + t * 32 + c0);
    hr[0] = make_float4(hv[0], hv[1], hv[2], hv[3]);
    hr[1] = make_float4(hv[4], hv[5], hv[6], hv[7]);
    __syncthreads();

    const int to = tid >> 3;
    const int oo = tid & 7;
    u64 acc0[6] = {0,0,0,0,0,0}, acc1[6] = {0,0,0,0,0,0};

    #pragma unroll 4
    for (int kd = 0; kd < 32; kd++) {
        float a0 = sh_h[2 * to][kd];
        float a1 = sh_h[2 * to + 1][kd];
        u64 ap0 = pack2(a0, a0), ap1 = pack2(a1, a1);
        const ulonglong2* wr = (const ulonglong2*)&sh_w[kd][oo * 12];
        ulonglong2 w0 = wr[0], w1 = wr[1], w2 = wr[2];
        u64 wv[6] = {w0.x, w0.y, w1.x, w1.y, w2.x, w2.y};
        #pragma unroll
        for (int i = 0; i < 6; i++) {
            acc0[i] = ffma2(ap0, wv[i], acc0[i]);
            acc1[i] = ffma2(ap1, wv[i], acc1[i]);
        }
    }

    const float QS = 0.51006973f;            // log2(e)/sqrt(8)
    const int b   = t0 >> 11;
    const int ttl = (t0 & 2047) + 2 * to;
    #pragma unroll
    for (int i2 = 0; i2 < 6; i2++) {
        int o    = oo * 12 + 2 * i2;
        int type = o >> 5;
        int head = (o >> 3) & 3;
        int kk   = o & 7;
        float* base = (type == 0) ? g_q : (type == 1) ? g_k : g_v;
        float sc = (type == 0) ? QS : 1.f;
        float2 u0 = unpack2(acc0[i2]);
        float2 u1 = unpack2(acc1[i2]);
        float* p = base + ((b * 4 + head) * 2048 + ttl) * 8 + kk;
        *(float2*)(p)     = make_float2(u0.x * sc, u0.y * sc);
        *(float2*)(p + 8) = make_float2(u1.x * sc, u1.y * sc);
    }
}

// ---------------------------------------------------------------------------
// Kernel 2: causal attention, f16 QK^T + f16 PV, f16x2 softmax, dbl-buffer.
// grid (32, 8), 256 threads (8 warps). Warp w owns query rows [16w,16w+16)
// of tiles j*128 (qa) and (15-j)*128 (qb). Loop key tiles kt=0..15-j.
// ---------------------------------------------------------------------------
static __device__ __forceinline__ void attn_dchunk(
    const u32* __restrict__ qf, u32 kb0, u32 kb1, const u32* __restrict__ vb,
    float* __restrict__ o, float& l0, float& l1,
    bool diag, int keybase, int r0, int tig2)
{
    float s0[4], s1[4];
    mma_qk_f16(s0, qf, kb0);
    mma_qk_f16(s1, qf, kb1);
    __half2 h0 = hex2(__floats2half2_rn(s0[0], s0[1]));   // row r0,   keys grp0
    __half2 h1 = hex2(__floats2half2_rn(s0[2], s0[3]));   // row r0+8, keys grp0
    __half2 h2 = hex2(__floats2half2_rn(s1[0], s1[1]));   // row r0,   keys grp1
    __half2 h3 = hex2(__floats2half2_rn(s1[2], s1[3]));   // row r0+8, keys grp1
    if (diag) {
        const int k0 = keybase + tig2;
        const int k1 = keybase + 8 + tig2;
        h0 = __hmul2(h0, mask2(k0, r0));
        h1 = __hmul2(h1, mask2(k0, r0 + 8));
        h2 = __hmul2(h2, mask2(k1, r0));
        h3 = __hmul2(h3, mask2(k1, r0 + 8));
    }
    {
        float2 f0 = __half22float2(__hadd2(h0, h2));
        l0 += f0.x + f0.y;
        float2 f1 = __half22float2(__hadd2(h1, h3));
        l1 += f1.x + f1.y;
    }
    u32 a[4] = { h2u(h0), h2u(h1), h2u(h2), h2u(h3) };
    mma_f16(o, a, vb);
}

__global__ __launch_bounds__(256) void k_attn()
{
    __shared__ u32 sKh[2][128 * 4];   // f16 K: [key][dim-pair], 4 half2/key
    __shared__ u32 sV [2][8 * 68];    // half2 V: [dim][keypair], stride 68

    const int tid = threadIdx.x;
    const int w   = tid >> 5;          // warp 0..7
    const int ln  = tid & 31;
    const int g   = ln >> 2;           // groupID 0..7
    const int tig = ln & 3;            // 0..3
    const int bh  = blockIdx.x;
    const int j   = blockIdx.y;        // query tiles j and 15-j
    const int jhi = 15 - j;

    const float* Qg = g_q + bh * T_ * 8;
    const int qa0 = j   * 128 + w * 16 + g;
    const int qb0 = jhi * 128 + w * 16 + g;

    // Q fragments (f16): a0 = row, dims 2tig..2tig+1; a1 = row+8
    u32 qaf[2], qbf[2];
    qaf[0] = h2u(__floats2half2_rn(Qg[(qa0)     * 8 + 2 * tig], Qg[(qa0)     * 8 + 2 * tig + 1]));
    qaf[1] = h2u(__floats2half2_rn(Qg[(qa0 + 8) * 8 + 2 * tig], Qg[(qa0 + 8) * 8 + 2 * tig + 1]));
    qbf[0] = h2u(__floats2half2_rn(Qg[(qb0)     * 8 + 2 * tig], Qg[(qb0)     * 8 + 2 * tig + 1]));
    qbf[1] = h2u(__floats2half2_rn(Qg[(qb0 + 8) * 8 + 2 * tig], Qg[(qb0 + 8) * 8 + 2 * tig + 1]));

    float oa[4] = {0.f, 0.f, 0.f, 0.f}, ob[4] = {0.f, 0.f, 0.f, 0.f};
    float la0 = 0.f, la1 = 0.f, lb0 = 0.f, lb1 = 0.f;

    const int srow  = tid >> 1;        // staging row (key) 0..127
    const int shalf = tid & 1;
    const float* Kr = g_k + (bh * T_ + srow) * 8 + shalf * 4;
    const float* Vr = g_v + (bh * T_ + srow) * 8 + shalf * 4;

    // prefetch tile 0
    float4 kreg = *(const float4*)(Kr);
    float4 vreg = *(const float4*)(Vr);

    for (int kt = 0; kt <= jhi; kt++) {
        const int s0 = kt * 128;
        const int buf = kt & 1;

        // ---- write staged registers into smem[buf] ----
        {
            // K as f16 dim-pairs: key srow, dims shalf*4 .. shalf*4+3
            u32* kd = &sKh[buf][srow * 4 + shalf * 2];
            kd[0] = h2u(__floats2half2_rn(kreg.x, kreg.y));
            kd[1] = h2u(__floats2half2_rn(kreg.z, kreg.w));
            // V as key-pair half2 (unchanged)
            float px = __shfl_xor_sync(0xffffffffu, vreg.x, 2);
            float py = __shfl_xor_sync(0xffffffffu, vreg.y, 2);
            float pz = __shfl_xor_sync(0xffffffffu, vreg.z, 2);
            float pw = __shfl_xor_sync(0xffffffffu, vreg.w, 2);
            if ((tid & 2) == 0) {            // even row of the key pair
                int kp = tid >> 2;
                int d0 = shalf * 4;
                sV[buf][(d0 + 0) * 68 + kp] = h2u(__floats2half2_rn(vreg.x, px));
                sV[buf][(d0 + 1) * 68 + kp] = h2u(__floats2half2_rn(vreg.y, py));
                sV[buf][(d0 + 2) * 68 + kp] = h2u(__floats2half2_rn(vreg.z, pz));
                sV[buf][(d0 + 3) * 68 + kp] = h2u(__floats2half2_rn(vreg.w, pw));
            }
        }
        __syncthreads();

        // ---- prefetch next tile (overlaps with compute below) ----
        if (kt < jhi) {
            kreg = *(const float4*)(Kr + (kt + 1) * 128 * 8);
            vreg = *(const float4*)(Vr + (kt + 1) * 128 * 8);
        }

        const bool qaAct = (kt <= j);
        const bool dA = (kt == j), dB = (kt == jhi);

        #pragma unroll 2
        for (int c = 0; c < 8; c++) {
            // B frags: key 16c+g (grp0) and 16c+8+g (grp1), dim-pair tig
            u32 kb0 = sKh[buf][(16 * c + g) * 4 + tig];
            u32 kb1 = sKh[buf][(16 * c + 8 + g) * 4 + tig];
            u32 vb[2];
            vb[0] = sV[buf][g * 68 + 8 * c + tig];
            vb[1] = sV[buf][g * 68 + 8 * c + tig + 4];

            if (qaAct)
                attn_dchunk(qaf, kb0, kb1, vb, oa, la0, la1, dA, s0 + 16 * c, qa0, 2 * tig);
            attn_dchunk(qbf, kb0, kb1, vb, ob, lb0, lb1, dB, s0 + 16 * c, qb0, 2 * tig);
        }
        // single sync per tile: next iteration writes smem[buf^1], whose
        // readers finished before this iteration's sync.
    }

    // ---- finalize: reduce l over the quad, normalize, store ----
    la0 += __shfl_xor_sync(0xffffffffu, la0, 1);
    la0 += __shfl_xor_sync(0xffffffffu, la0, 2);
    la1 += __shfl_xor_sync(0xffffffffu, la1, 1);
    la1 += __shfl_xor_sync(0xffffffffu, la1, 2);
    lb0 += __shfl_xor_sync(0xffffffffu, lb0, 1);
    lb0 += __shfl_xor_sync(0xffffffffu, lb0, 2);
    lb1 += __shfl_xor_sync(0xffffffffu, lb1, 1);
    lb1 += __shfl_xor_sync(0xffffffffu, lb1, 2);
    const float ra0 = __fdividef(1.f, la0);
    const float ra1 = __fdividef(1.f, la1);
    const float rb0 = __fdividef(1.f, lb0);
    const float rb1 = __fdividef(1.f, lb1);

    const int bb = bh >> 2, h = bh & 3;
    const int colo = h * 8 + 2 * tig;
    *(float2*)(g_o + (bb * T_ + qa0)     * 32 + colo) = make_float2(oa[0] * ra0, oa[1] * ra0);
    *(float2*)(g_o + (bb * T_ + qa0 + 8) * 32 + colo) = make_float2(oa[2] * ra1, oa[3] * ra1);
    *(float2*)(g_o + (bb * T_ + qb0)     * 32 + colo) = make_float2(ob[0] * rb0, ob[1] * rb0);
    *(float2*)(g_o + (bb * T_ + qb0 + 8) * 32 + colo) = make_float2(ob[2] * rb1, ob[3] * rb1);
}

// ---------------------------------------------------------------------------
// Kernel 3: proj + residual + LN2 + FFN + residual. 32 tokens, 256 threads,
// grid 512. (unchanged)
// ---------------------------------------------------------------------------
constexpr int SM3_FLOATS = 1024 + 4096 + 4096 + 128 + 128 + 32 * 33 + 32 * 129;
constexpr int SM3_BYTES  = SM3_FLOATS * 4;

__global__ __launch_bounds__(256) void k_post(
    float* __restrict__ out,
    const float* __restrict__ Wp, const float* __restrict__ bp,
    const float* __restrict__ W1, const float* __restrict__ b1v,
    const float* __restrict__ W2, const float* __restrict__ b2v,
    const float* __restrict__ g2, const float* __restrict__ bt2)
{
    extern __shared__ float sm[];
    float* sWp  = sm;
    float* sW1  = sWp + 1024;
    float* sW2  = sW1 + 4096;
    float* sB   = sW2 + 4096;
    float* sb1  = sB + 128;
    float* sX   = sb1 + 128;
    float* sHid = sX + 32 * 33;

    const int tid = threadIdx.x;
    const int t0  = blockIdx.x * 32;

    *(float4*)&sWp[tid * 4] = *(const float4*)(Wp + tid * 4);
    for (int i4 = tid; i4 < 1024; i4 += 256)
        *(float4*)&sW1[i4 * 4] = *(const float4*)(W1 + i4 * 4);
    for (int i4 = tid; i4 < 1024; i4 += 256)
        *(float4*)&sW2[i4 * 4] = *(const float4*)(W2 + i4 * 4);
    if (tid < 32) { sB[tid] = bp[tid]; sB[32 + tid] = b2v[tid];
                    sB[64 + tid] = g2[tid]; sB[96 + tid] = bt2[tid]; }
    if (tid >= 128 && tid < 256) sb1[tid - 128] = b1v[tid - 128];

    {
        int row = tid >> 3, c4 = tid & 7;
        float4 v = ((const float4*)(g_o + (t0 + row) * 32))[c4];
        float* d = &sX[row * 33 + c4 * 4];
        d[0] = v.x; d[1] = v.y; d[2] = v.z; d[3] = v.w;
    }
    __syncthreads();

    const int tr = tid >> 3, q8 = tid & 7;
    const int c0 = q8 * 4;
    const int gt = t0 + tr;
    u64 accp[2] = {0, 0};

    #pragma unroll 4
    for (int kd = 0; kd < 32; kd++) {
        float a = sX[tr * 33 + kd];
        u64 ap = pack2(a, a);
        ulonglong2 w0 = *(const ulonglong2*)&sWp[kd * 32 + c0];
        accp[0] = ffma2(ap, w0.x, accp[0]);
        accp[1] = ffma2(ap, w0.y, accp[1]);
    }
    float xv[4];
    {
        float4 h0 = *(const float4*)(g_h + gt * 32 + c0);
        float2 u0 = unpack2(accp[0]), u1 = unpack2(accp[1]);
        xv[0] = h0.x + u0.x + sB[c0 + 0];
        xv[1] = h0.y + u0.y + sB[c0 + 1];
        xv[2] = h0.z + u1.x + sB[c0 + 2];
        xv[3] = h0.w + u1.y + sB[c0 + 3];
    }
    float s = 0.f, ss = 0.f;
    #pragma unroll
    for (int i = 0; i < 4; i++) { s += xv[i]; ss += xv[i] * xv[i]; }
    s  += __shfl_xor_sync(0xffffffffu, s, 1);
    ss += __shfl_xor_sync(0xffffffffu, ss, 1);
    s  += __shfl_xor_sync(0xffffffffu, s, 2);
    ss += __shfl_xor_sync(0xffffffffu, ss, 2);
    s  += __shfl_xor_sync(0xffffffffu, s, 4);
    ss += __shfl_xor_sync(0xffffffffu, ss, 4);
    const float mu = s * 0.03125f;
    const float rs = rsqrtf(ss * 0.03125f - mu * mu + 1e-5f);
    float h2r[4];
    #pragma unroll
    for (int i = 0; i < 4; i++)
        h2r[i] = (xv[i] - mu) * rs * sB[64 + c0 + i] + sB[96 + c0 + i];

    __syncthreads();
    #pragma unroll
    for (int i = 0; i < 4; i++) sX[tr * 33 + c0 + i] = h2r[i];
    __syncthreads();

    const int ttb = tid >> 4;
    const int oo  = tid & 15;
    u64 accB[2][4];
    #pragma unroll
    for (int j = 0; j < 2; j++)
        #pragma unroll
        for (int i = 0; i < 4; i++) accB[j][i] = 0;

    #pragma unroll 4
    for (int k = 0; k < 32; k++) {
        float a0 = sX[(ttb * 2 + 0) * 33 + k];
        float a1 = sX[(ttb * 2 + 1) * 33 + k];
        u64 ap0 = pack2(a0, a0), ap1 = pack2(a1, a1);
        const ulonglong2* wr = (const ulonglong2*)&sW1[k * 128 + oo * 8];
        ulonglong2 ww0 = wr[0], ww1 = wr[1];
        u64 wv[4] = {ww0.x, ww0.y, ww1.x, ww1.y};
        #pragma unroll
        for (int i = 0; i < 4; i++) {
            accB[0][i] = ffma2(ap0, wv[i], accB[0][i]);
            accB[1][i] = ffma2(ap1, wv[i], accB[1][i]);
        }
    }
    #pragma unroll
    for (int j = 0; j < 2; j++)
        #pragma unroll
        for (int i = 0; i < 4; i++) {
            float2 u = unpack2(accB[j][i]);
            float* d = &sHid[(ttb * 2 + j) * 129 + oo * 8 + 2 * i];
            d[0] = fmaxf(u.x + sb1[oo * 8 + 2 * i], 0.f);
            d[1] = fmaxf(u.y + sb1[oo * 8 + 2 * i + 1], 0.f);
        }
    __syncthreads();

    u64 accC[2] = {0, 0};
    #pragma unroll 4
    for (int k = 0; k < 128; k++) {
        float a = sHid[tr * 129 + k];
        u64 ap = pack2(a, a);
        ulonglong2 w0 = *(const ulonglong2*)&sW2[k * 32 + c0];
        accC[0] = ffma2(ap, w0.x, accC[0]);
        accC[1] = ffma2(ap, w0.y, accC[1]);
    }
    float2 u0 = unpack2(accC[0]), u1 = unpack2(accC[1]);
    *(float4*)(out + gt * 32 + c0) = make_float4(
        h2r[0] + u0.x + sB[32 + c0 + 0],
        h2r[1] + u0.y + sB[32 + c0 + 1],
        h2r[2] + u1.x + sB[32 + c0 + 2],
        h2r[3] + u1.y + sB[32 + c0 + 3]);
}

// ---------------------------------------------------------------------------
extern "C" void kernel_launch(void* const* d_in, const int* in_sizes, int n_in,
                              void* d_out, int out_size)
{
    const float* x   = (const float*)d_in[0];
    const float* Wq  = (const float*)d_in[1];
    const float* Wk  = (const float*)d_in[2];
    const float* Wv  = (const float*)d_in[3];
    const float* Wp  = (const float*)d_in[4];
    const float* bp  = (const float*)d_in[5];
    const float* g1  = (const float*)d_in[6];
    const float* b1  = (const float*)d_in[7];
    const float* W1  = (const float*)d_in[8];
    const float* b1f = (const float*)d_in[9];
    const float* W2  = (const float*)d_in[10];
    const float* b2f = (const float*)d_in[11];
    const float* g2  = (const float*)d_in[12];
    const float* bt2 = (const float*)d_in[13];
    float* out = (float*)d_out;

    cudaFuncSetAttribute((const void*)k_post,
                         cudaFuncAttributeMaxDynamicSharedMemorySize, SM3_BYTES);

    k_ln_qkv<<<BT_ / 32, 128>>>(x, Wq, Wk, Wv, g1, b1);

    dim3 ga(B_ * 4, 8);
    k_attn<<<ga, 256>>>();

    k_post<<<BT_ / 32, 256, SM3_BYTES>>>(out, Wp, bp, W1, b1f, W2, b2f, g2, bt2);
}

// round 16
// speedup vs baseline: 1.1474x; 1.1153x over previous
#include <cuda_runtime.h>
#include <cuda_fp16.h>

// ---------------------------------------------------------------------------
// DecoderBlock fused persistent kernel: x:(8,2048,32), H=4, hd=8.
// One launch, 256 blocks x 256 threads, device-wide generation barriers.
// Phase1: LN1+QKV (SIMT f32x2, half-block per 32-token group).
// Phase2: causal attention (f16 QK^T mma + f16x2 ex2 + f16 PV mma, pairing).
// Phase3: proj+LN2+FFN (SIMT f32x2, half-block per 32-token tile).
// ---------------------------------------------------------------------------

constexpr int B_  = 8;
constexpr int T_  = 2048;
constexpr int D_  = 32;
constexpr int BT_ = B_ * T_;
constexpr int NBLK = 256;

__device__ float g_h[BT_ * D_];
__device__ float g_q[BT_ * D_];   // (B,H,T,8), pre-scaled by log2e/sqrt(8)
__device__ float g_k[BT_ * D_];
__device__ float g_v[BT_ * D_];
__device__ float g_o[BT_ * D_];

__device__ volatile unsigned g_bar_gen = 0;
__device__ unsigned g_bar_cnt = 0;

typedef unsigned long long u64;
typedef unsigned int u32;

static __device__ __forceinline__ u64 ffma2(u64 a, u64 b, u64 c) {
    u64 d; asm("fma.rn.f32x2 %0, %1, %2, %3;" : "=l"(d) : "l"(a), "l"(b), "l"(c));
    return d;
}
static __device__ __forceinline__ u64 pack2(float x, float y) {
    u64 d; asm("mov.b64 %0, {%1, %2};" : "=l"(d) : "f"(x), "f"(y));
    return d;
}
static __device__ __forceinline__ float2 unpack2(u64 d) {
    float2 r; asm("mov.b64 {%0, %1}, %2;" : "=f"(r.x), "=f"(r.y) : "l"(d));
    return r;
}
static __device__ __forceinline__ u32 h2u(__half2 h) {
    u32 u; __builtin_memcpy(&u, &h, 4); return u;
}
static __device__ __forceinline__ __half2 u2h(u32 u) {
    __half2 h; __builtin_memcpy(&h, &u, 4); return h;
}
static __device__ __forceinline__ __half2 hex2(__half2 h) {
    u32 u = h2u(h);
    asm("ex2.approx.f16x2 %0, %0;" : "+r"(u));
    return u2h(u);
}
static __device__ __forceinline__ __half2 mask2(int k, int r) {
    u32 m = (k + 1 <= r) ? 0x3C003C00u : ((k <= r) ? 0x00003C00u : 0u);
    return u2h(m);
}
static __device__ __forceinline__ void mma_qk_f16(float* d, const u32* a, u32 b) {
    asm("mma.sync.aligned.m16n8k8.row.col.f32.f16.f16.f32 "
        "{%0,%1,%2,%3}, {%4,%5}, {%6}, {%7,%8,%9,%10};"
        : "=f"(d[0]), "=f"(d[1]), "=f"(d[2]), "=f"(d[3])
        : "r"(a[0]), "r"(a[1]), "r"(b),
          "f"(0.f), "f"(0.f), "f"(0.f), "f"(0.f));
}
static __device__ __forceinline__ void mma_f16(float* d, const u32* a, const u32* b) {
    asm("mma.sync.aligned.m16n8k16.row.col.f32.f16.f16.f32 "
        "{%0,%1,%2,%3}, {%4,%5,%6,%7}, {%8,%9}, {%0,%1,%2,%3};"
        : "+f"(d[0]), "+f"(d[1]), "+f"(d[2]), "+f"(d[3])
        : "r"(a[0]), "r"(a[1]), "r"(a[2]), "r"(a[3]),
          "r"(b[0]), "r"(b[1]));
}

// generation-based grid barrier (all NBLK blocks must be resident)
static __device__ __forceinline__ void grid_barrier() {
    __syncthreads();
    if (threadIdx.x == 0) {
        __threadfence();
        unsigned gen = g_bar_gen;
        if (atomicAdd(&g_bar_cnt, 1u) == (unsigned)(NBLK - 1)) {
            g_bar_cnt = 0;
            __threadfence();
            g_bar_gen = gen + 1;
        } else {
            while (g_bar_gen == gen) { }
        }
        __threadfence();
    }
    __syncthreads();
}

// smem: 79360 bytes (phase-3 footprint is the max)
constexpr int SMEM_FLOATS = 9472 + 2 * 5184;
constexpr int SMEM_BYTES  = SMEM_FLOATS * 4;

static __device__ __forceinline__ void attn_dchunk(
    const u32* __restrict__ qf, u32 kb0, u32 kb1, const u32* __restrict__ vb,
    float* __restrict__ o, float& l0, float& l1,
    bool diag, int keybase, int r0, int tig2)
{
    float s0[4], s1[4];
    mma_qk_f16(s0, qf, kb0);
    mma_qk_f16(s1, qf, kb1);
    __half2 h0 = hex2(__floats2half2_rn(s0[0], s0[1]));
    __half2 h1 = hex2(__floats2half2_rn(s0[2], s0[3]));
    __half2 h2 = hex2(__floats2half2_rn(s1[0], s1[1]));
    __half2 h3 = hex2(__floats2half2_rn(s1[2], s1[3]));
    if (diag) {
        const int k0 = keybase + tig2;
        const int k1 = keybase + 8 + tig2;
        h0 = __hmul2(h0, mask2(k0, r0));
        h1 = __hmul2(h1, mask2(k0, r0 + 8));
        h2 = __hmul2(h2, mask2(k1, r0));
        h3 = __hmul2(h3, mask2(k1, r0 + 8));
    }
    {
        float2 f0 = __half22float2(__hadd2(h0, h2));
        l0 += f0.x + f0.y;
        float2 f1 = __half22float2(__hadd2(h1, h3));
        l1 += f1.x + f1.y;
    }
    u32 a[4] = { h2u(h0), h2u(h1), h2u(h2), h2u(h3) };
    mma_f16(o, a, vb);
}

__global__ __launch_bounds__(256, 2) void k_fused(
    float* __restrict__ out,
    const float* __restrict__ x,
    const float* __restrict__ Wq, const float* __restrict__ Wk,
    const float* __restrict__ Wv,
    const float* __restrict__ g1, const float* __restrict__ b1,
    const float* __restrict__ Wp, const float* __restrict__ bp,
    const float* __restrict__ W1, const float* __restrict__ b1v,
    const float* __restrict__ W2, const float* __restrict__ b2v,
    const float* __restrict__ g2, const float* __restrict__ bt2)
{
    extern __shared__ float sm[];
    const int tid  = threadIdx.x;
    const int bid  = blockIdx.x;
    const int half = tid >> 7;
    const int ht   = tid & 127;

    // =====================================================================
    // Phase 1: LN1 + QKV.  Half-block = one 32-token group (2 per block).
    // =====================================================================
    {
        float* sh_w = sm;                          // [32][96]
        float* sh_h = sm + 3072 + half * 1056;     // [32][33] per half

        // stage combined qkv weights (whole block)
        for (int i4 = tid; i4 < 768; i4 += 256) {
            int i = i4 * 4;
            int type = i >> 10, rem = i & 1023;
            int head = rem >> 8, d = (rem >> 3) & 31, kk = rem & 7;
            const float* W = (type == 0) ? Wq : (type == 1) ? Wk : Wv;
            *(float4*)&sh_w[d * 96 + type * 32 + head * 8 + kk] = *(const float4*)(W + rem);
        }
        __syncthreads();

        const int t0 = (bid * 2 + half) * 32;
        const int tk = ht >> 2, part = ht & 3;
        const int t  = t0 + tk;
        const int c0 = part * 8;
        const float4* xr = (const float4*)(x + t * 32 + c0);
        float4 v0 = xr[0], v1 = xr[1];
        float s  = v0.x + v0.y + v0.z + v0.w + v1.x + v1.y + v1.z + v1.w;
        float ss = v0.x*v0.x + v0.y*v0.y + v0.z*v0.z + v0.w*v0.w
                 + v1.x*v1.x + v1.y*v1.y + v1.z*v1.z + v1.w*v1.w;
        s  += __shfl_xor_sync(0xffffffffu, s, 1);
        ss += __shfl_xor_sync(0xffffffffu, ss, 1);
        s  += __shfl_xor_sync(0xffffffffu, s, 2);
        ss += __shfl_xor_sync(0xffffffffu, ss, 2);
        const float mu = s * 0.03125f;
        const float rs = rsqrtf(ss * 0.03125f - mu * mu + 1e-5f);
        float hv[8];
        {
            const float* vv = (const float*)&v0;
            #pragma unroll
            for (int i = 0; i < 4; i++)
                hv[i] = (vv[i] - mu) * rs * __ldg(g1 + c0 + i) + __ldg(b1 + c0 + i);
            const float* vw = (const float*)&v1;
            #pragma unroll
            for (int i = 0; i < 4; i++)
                hv[4 + i] = (vw[i] - mu) * rs * __ldg(g1 + c0 + 4 + i) + __ldg(b1 + c0 + 4 + i);
        }
        #pragma unroll
        for (int i = 0; i < 8; i++) sh_h[tk * 33 + c0 + i] = hv[i];
        float4* hr = (float4*)(g_h + t * 32 + c0);
        hr[0] = make_float4(hv[0], hv[1], hv[2], hv[3]);
        hr[1] = make_float4(hv[4], hv[5], hv[6], hv[7]);
        asm volatile("bar.sync %0, 128;" :: "r"(1 + half) : "memory");

        const int to = ht >> 3;
        const int oo = ht & 7;
        u64 acc0[6] = {0,0,0,0,0,0}, acc1[6] = {0,0,0,0,0,0};
        #pragma unroll 4
        for (int kd = 0; kd < 32; kd++) {
            float a0 = sh_h[2 * to * 33 + kd];
            float a1 = sh_h[(2 * to + 1) * 33 + kd];
            u64 ap0 = pack2(a0, a0), ap1 = pack2(a1, a1);
            const ulonglong2* wr = (const ulonglong2*)&sh_w[kd * 96 + oo * 12];
            ulonglong2 w0 = wr[0], w1 = wr[1], w2 = wr[2];
            u64 wv[6] = {w0.x, w0.y, w1.x, w1.y, w2.x, w2.y};
            #pragma unroll
            for (int i = 0; i < 6; i++) {
                acc0[i] = ffma2(ap0, wv[i], acc0[i]);
                acc1[i] = ffma2(ap1, wv[i], acc1[i]);
            }
        }
        const float QS = 0.51006973f;          // log2(e)/sqrt(8)
        const int b   = t0 >> 11;
        const int ttl = (t0 & 2047) + 2 * to;
        #pragma unroll
        for (int i2 = 0; i2 < 6; i2++) {
            int o    = oo * 12 + 2 * i2;
            int type = o >> 5;
            int head = (o >> 3) & 3;
            int kk   = o & 7;
            float* base = (type == 0) ? g_q : (type == 1) ? g_k : g_v;
            float sc = (type == 0) ? QS : 1.f;
            float2 u0 = unpack2(acc0[i2]);
            float2 u1 = unpack2(acc1[i2]);
            float* p = base + ((b * 4 + head) * 2048 + ttl) * 8 + kk;
            *(float2*)(p)     = make_float2(u0.x * sc, u0.y * sc);
            *(float2*)(p + 8) = make_float2(u1.x * sc, u1.y * sc);
        }
    }

    grid_barrier();

    // =====================================================================
    // Phase 2: causal attention, balanced pairing (tiles j and 15-j).
    // =====================================================================
    {
        u32* su  = (u32*)sm;
        u32* sKh = su;           // [2][128*4]
        u32* sV  = su + 1024;    // [2][8*68]

        const int w   = tid >> 5;
        const int ln  = tid & 31;
        const int g   = ln >> 2;
        const int tig = ln & 3;
        const int bh  = bid & 31;
        const int j   = bid >> 5;          // 0..7
        const int jhi = 15 - j;

        const float* Qg = g_q + bh * T_ * 8;
        const int qa0 = j   * 128 + w * 16 + g;
        const int qb0 = jhi * 128 + w * 16 + g;

        u32 qaf[2], qbf[2];
        qaf[0] = h2u(__floats2half2_rn(Qg[(qa0)     * 8 + 2 * tig], Qg[(qa0)     * 8 + 2 * tig + 1]));
        qaf[1] = h2u(__floats2half2_rn(Qg[(qa0 + 8) * 8 + 2 * tig], Qg[(qa0 + 8) * 8 + 2 * tig + 1]));
        qbf[0] = h2u(__floats2half2_rn(Qg[(qb0)     * 8 + 2 * tig], Qg[(qb0)     * 8 + 2 * tig + 1]));
        qbf[1] = h2u(__floats2half2_rn(Qg[(qb0 + 8) * 8 + 2 * tig], Qg[(qb0 + 8) * 8 + 2 * tig + 1]));

        float oa[4] = {0.f, 0.f, 0.f, 0.f}, ob[4] = {0.f, 0.f, 0.f, 0.f};
        float la0 = 0.f, la1 = 0.f, lb0 = 0.f, lb1 = 0.f;

        const int srow  = tid >> 1;
        const int shalf = tid & 1;
        const float* Kr = g_k + (bh * T_ + srow) * 8 + shalf * 4;
        const float* Vr = g_v + (bh * T_ + srow) * 8 + shalf * 4;

        float4 kreg = *(const float4*)(Kr);
        float4 vreg = *(const float4*)(Vr);

        for (int kt = 0; kt <= jhi; kt++) {
            const int s0 = kt * 128;
            const int buf = kt & 1;
            {
                u32* kd = &sKh[buf * 512 + srow * 4 + shalf * 2];
                kd[0] = h2u(__floats2half2_rn(kreg.x, kreg.y));
                kd[1] = h2u(__floats2half2_rn(kreg.z, kreg.w));
                float px = __shfl_xor_sync(0xffffffffu, vreg.x, 2);
                float py = __shfl_xor_sync(0xffffffffu, vreg.y, 2);
                float pz = __shfl_xor_sync(0xffffffffu, vreg.z, 2);
                float pw = __shfl_xor_sync(0xffffffffu, vreg.w, 2);
                if ((tid & 2) == 0) {
                    int kp = tid >> 2;
                    int d0 = shalf * 4;
                    sV[buf * 544 + (d0 + 0) * 68 + kp] = h2u(__floats2half2_rn(vreg.x, px));
                    sV[buf * 544 + (d0 + 1) * 68 + kp] = h2u(__floats2half2_rn(vreg.y, py));
                    sV[buf * 544 + (d0 + 2) * 68 + kp] = h2u(__floats2half2_rn(vreg.z, pz));
                    sV[buf * 544 + (d0 + 3) * 68 + kp] = h2u(__floats2half2_rn(vreg.w, pw));
                }
            }
            __syncthreads();

            if (kt < jhi) {
                kreg = *(const float4*)(Kr + (kt + 1) * 128 * 8);
                vreg = *(const float4*)(Vr + (kt + 1) * 128 * 8);
            }

            const bool qaAct = (kt <= j);
            const bool dA = (kt == j), dB = (kt == jhi);

            #pragma unroll 2
            for (int c = 0; c < 8; c++) {
                u32 kb0 = sKh[buf * 512 + (16 * c + g) * 4 + tig];
                u32 kb1 = sKh[buf * 512 + (16 * c + 8 + g) * 4 + tig];
                u32 vb[2];
                vb[0] = sV[buf * 544 + g * 68 + 8 * c + tig];
                vb[1] = sV[buf * 544 + g * 68 + 8 * c + tig + 4];
                if (qaAct)
                    attn_dchunk(qaf, kb0, kb1, vb, oa, la0, la1, dA, s0 + 16 * c, qa0, 2 * tig);
                attn_dchunk(qbf, kb0, kb1, vb, ob, lb0, lb1, dB, s0 + 16 * c, qb0, 2 * tig);
            }
        }

        la0 += __shfl_xor_sync(0xffffffffu, la0, 1);
        la0 += __shfl_xor_sync(0xffffffffu, la0, 2);
        la1 += __shfl_xor_sync(0xffffffffu, la1, 1);
        la1 += __shfl_xor_sync(0xffffffffu, la1, 2);
        lb0 += __shfl_xor_sync(0xffffffffu, lb0, 1);
        lb0 += __shfl_xor_sync(0xffffffffu, lb0, 2);
        lb1 += __shfl_xor_sync(0xffffffffu, lb1, 1);
        lb1 += __shfl_xor_sync(0xffffffffu, lb1, 2);
        const float ra0 = __fdividef(1.f, la0);
        const float ra1 = __fdividef(1.f, la1);
        const float rb0 = __fdividef(1.f, lb0);
        const float rb1 = __fdividef(1.f, lb1);

        const int bb = bh >> 2, h = bh & 3;
        const int colo = h * 8 + 2 * tig;
        *(float2*)(g_o + (bb * T_ + qa0)     * 32 + colo) = make_float2(oa[0] * ra0, oa[1] * ra0);
        *(float2*)(g_o + (bb * T_ + qa0 + 8) * 32 + colo) = make_float2(oa[2] * ra1, oa[3] * ra1);
        *(float2*)(g_o + (bb * T_ + qb0)     * 32 + colo) = make_float2(ob[0] * rb0, ob[1] * rb0);
        *(float2*)(g_o + (bb * T_ + qb0 + 8) * 32 + colo) = make_float2(ob[2] * rb1, ob[3] * rb1);
    }

    grid_barrier();

    // =====================================================================
    // Phase 3: proj + residual + LN2 + FFN + residual.
    // Half-block = one 32-token tile (2 per block), weights shared.
    // =====================================================================
    {
        float* sWp = sm;                 // [32][32]
        float* sW1 = sWp + 1024;         // [32][128]
        float* sW2 = sW1 + 4096;         // [128][32]
        float* sB  = sW2 + 4096;         // biases
        float* sb1 = sB + 128;
        float* sX  = sb1 + 128 + half * 5184;   // [32][33]
        float* sHid = sX + 1056;                 // [32][129]

        // stage weights (whole block)
        *(float4*)&sWp[tid * 4] = *(const float4*)(Wp + tid * 4);
        for (int i4 = tid; i4 < 1024; i4 += 256)
            *(float4*)&sW1[i4 * 4] = *(const float4*)(W1 + i4 * 4);
        for (int i4 = tid; i4 < 1024; i4 += 256)
            *(float4*)&sW2[i4 * 4] = *(const float4*)(W2 + i4 * 4);
        if (tid < 32) { sB[tid] = bp[tid]; sB[32 + tid] = b2v[tid];
                        sB[64 + tid] = g2[tid]; sB[96 + tid] = bt2[tid]; }
        if (tid >= 128 && tid < 256) sb1[tid - 128] = b1v[tid - 128];
        __syncthreads();

        const int t0  = (bid * 2 + half) * 32;
        const int bar = 1 + half;

        // o tile -> sX: 256 float4 per tile / 128 threads = 2 each
        #pragma unroll
        for (int r = 0; r < 2; r++) {
            int idx = ht + 128 * r;
            int row = idx >> 3, c4 = idx & 7;
            float4 v = ((const float4*)(g_o + (t0 + row) * 32))[c4];
            float* d = &sX[row * 33 + c4 * 4];
            d[0] = v.x; d[1] = v.y; d[2] = v.z; d[3] = v.w;
        }
        asm volatile("bar.sync %0, 128;" :: "r"(bar) : "memory");

        // ---- stage A: x1 = h + o@Wproj + bproj ; h2 = LN2(x1) ----
        const int tr = ht >> 2, q4 = ht & 3;   // token, col-quarter (8 cols)
        const int c0 = q4 * 8;
        const int gt = t0 + tr;
        u64 accp[4] = {0, 0, 0, 0};
        #pragma unroll 4
        for (int kd = 0; kd < 32; kd++) {
            float a = sX[tr * 33 + kd];
            u64 ap = pack2(a, a);
            const ulonglong2* wr = (const ulonglong2*)&sWp[kd * 32 + c0];
            ulonglong2 w0 = wr[0], w1 = wr[1];
            accp[0] = ffma2(ap, w0.x, accp[0]); accp[1] = ffma2(ap, w0.y, accp[1]);
            accp[2] = ffma2(ap, w1.x, accp[2]); accp[3] = ffma2(ap, w1.y, accp[3]);
        }
        float xv[8];
        {
            const float4* hp = (const float4*)(g_h + gt * 32 + c0);
            float4 h0 = hp[0], h1 = hp[1];
            float2 u0 = unpack2(accp[0]), u1 = unpack2(accp[1]);
            float2 u2 = unpack2(accp[2]), u3 = unpack2(accp[3]);
            xv[0] = h0.x + u0.x + sB[c0 + 0];
            xv[1] = h0.y + u0.y + sB[c0 + 1];
            xv[2] = h0.z + u1.x + sB[c0 + 2];
            xv[3] = h0.w + u1.y + sB[c0 + 3];
            xv[4] = h1.x + u2.x + sB[c0 + 4];
            xv[5] = h1.y + u2.y + sB[c0 + 5];
            xv[6] = h1.z + u3.x + sB[c0 + 6];
            xv[7] = h1.w + u3.y + sB[c0 + 7];
        }
        float s = 0.f, ss = 0.f;
        #pragma unroll
        for (int i = 0; i < 8; i++) { s += xv[i]; ss += xv[i] * xv[i]; }
        s  += __shfl_xor_sync(0xffffffffu, s, 1);
        ss += __shfl_xor_sync(0xffffffffu, ss, 1);
        s  += __shfl_xor_sync(0xffffffffu, s, 2);
        ss += __shfl_xor_sync(0xffffffffu, ss, 2);
        const float mu = s * 0.03125f;
        const float rs = rsqrtf(ss * 0.03125f - mu * mu + 1e-5f);
        float h2r[8];
        #pragma unroll
        for (int i = 0; i < 8; i++)
            h2r[i] = (xv[i] - mu) * rs * sB[64 + c0 + i] + sB[96 + c0 + i];

        asm volatile("bar.sync %0, 128;" :: "r"(bar) : "memory");
        #pragma unroll
        for (int i = 0; i < 8; i++) sX[tr * 33 + c0 + i] = h2r[i];
        asm volatile("bar.sync %0, 128;" :: "r"(bar) : "memory");

        // ---- stage B: hid = relu(h2 @ W1 + b1) ----
        const int ttb = ht >> 4;   // 0..7 -> 4 tokens each
        const int oo  = ht & 15;   // 8 outs each
        u64 accB[4][4];
        #pragma unroll
        for (int jj = 0; jj < 4; jj++)
            #pragma unroll
            for (int i = 0; i < 4; i++) accB[jj][i] = 0;
        #pragma unroll 4
        for (int k = 0; k < 32; k++) {
            u64 ap[4];
            #pragma unroll
            for (int jj = 0; jj < 4; jj++) {
                float a = sX[(ttb * 4 + jj) * 33 + k];
                ap[jj] = pack2(a, a);
            }
            const ulonglong2* wr = (const ulonglong2*)&sW1[k * 128 + oo * 8];
            ulonglong2 ww0 = wr[0], ww1 = wr[1];
            u64 wv[4] = {ww0.x, ww0.y, ww1.x, ww1.y};
            #pragma unroll
            for (int jj = 0; jj < 4; jj++)
                #pragma unroll
                for (int i = 0; i < 4; i++)
                    accB[jj][i] = ffma2(ap[jj], wv[i], accB[jj][i]);
        }
        #pragma unroll
        for (int jj = 0; jj < 4; jj++)
            #pragma unroll
            for (int i = 0; i < 4; i++) {
                float2 u = unpack2(accB[jj][i]);
                float* d = &sHid[(ttb * 4 + jj) * 129 + oo * 8 + 2 * i];
                d[0] = fmaxf(u.x + sb1[oo * 8 + 2 * i], 0.f);
                d[1] = fmaxf(u.y + sb1[oo * 8 + 2 * i + 1], 0.f);
            }
        asm volatile("bar.sync %0, 128;" :: "r"(bar) : "memory");

        // ---- stage C: out = h2 + hid @ W2 + b2 ----
        u64 accC[4] = {0, 0, 0, 0};
        #pragma unroll 4
        for (int k = 0; k < 128; k++) {
            float a = sHid[tr * 129 + k];
            u64 ap = pack2(a, a);
            const ulonglong2* wr = (const ulonglong2*)&sW2[k * 32 + c0];
            ulonglong2 w0 = wr[0], w1 = wr[1];
            accC[0] = ffma2(ap, w0.x, accC[0]); accC[1] = ffma2(ap, w0.y, accC[1]);
            accC[2] = ffma2(ap, w1.x, accC[2]); accC[3] = ffma2(ap, w1.y, accC[3]);
        }
        float2 u0 = unpack2(accC[0]), u1 = unpack2(accC[1]);
        float2 u2 = unpack2(accC[2]), u3 = unpack2(accC[3]);
        float4* op = (float4*)(out + gt * 32 + c0);
        op[0] = make_float4(h2r[0] + u0.x + sB[32 + c0 + 0],
                            h2r[1] + u0.y + sB[32 + c0 + 1],
                            h2r[2] + u1.x + sB[32 + c0 + 2],
                            h2r[3] + u1.y + sB[32 + c0 + 3]);
        op[1] = make_float4(h2r[4] + u2.x + sB[32 + c0 + 4],
                            h2r[5] + u2.y + sB[32 + c0 + 5],
                            h2r[6] + u3.x + sB[32 + c0 + 6],
                            h2r[7] + u3.y + sB[32 + c0 + 7]);
    }
}

// ---------------------------------------------------------------------------
extern "C" void kernel_launch(void* const* d_in, const int* in_sizes, int n_in,
                              void* d_out, int out_size)
{
    const float* x   = (const float*)d_in[0];
    const float* Wq  = (const float*)d_in[1];
    const float* Wk  = (const float*)d_in[2];
    const float* Wv  = (const float*)d_in[3];
    const float* Wp  = (const float*)d_in[4];
    const float* bp  = (const float*)d_in[5];
    const float* g1  = (const float*)d_in[6];
    const float* b1  = (const float*)d_in[7];
    const float* W1  = (const float*)d_in[8];
    const float* b1f = (const float*)d_in[9];
    const float* W2  = (const float*)d_in[10];
    const float* b2f = (const float*)d_in[11];
    const float* g2  = (const float*)d_in[12];
    const float* bt2 = (const float*)d_in[13];
    float* out = (float*)d_out;

    cudaFuncSetAttribute((const void*)k_fused,
                         cudaFuncAttributeMaxDynamicSharedMemorySize, SMEM_BYTES);

    k_fused<<<NBLK, 256, SMEM_BYTES>>>(out, x, Wq, Wk, Wv, g1, b1,
                                       Wp, bp, W1, b1f, W2, b2f, g2, bt2);
}

// round 17
// speedup vs baseline: 1.1855x; 1.0332x over previous
#include <cuda_runtime.h>
#include <cuda_fp16.h>

// ---------------------------------------------------------------------------
// DecoderBlock fused persistent kernel: x:(8,2048,32), H=4, hd=8.
// One launch, 256 blocks x 256 threads, device-wide generation barriers.
// Phase1: LN1+QKV (SIMT f32x2) + smem-bounce coalesced q/k/v stores.
// Phase2: causal attention (f16 QK^T mma + f16x2 ex2 + f16 PV mma, pairing).
// Phase3: proj+LN2+FFN (SIMT f32x2, half-block per 32-token tile).
// ---------------------------------------------------------------------------

constexpr int B_  = 8;
constexpr int T_  = 2048;
constexpr int D_  = 32;
constexpr int BT_ = B_ * T_;
constexpr int NBLK = 256;

__device__ float g_h[BT_ * D_];
__device__ float g_q[BT_ * D_];   // (B,H,T,8), pre-scaled by log2e/sqrt(8)
__device__ float g_k[BT_ * D_];
__device__ float g_v[BT_ * D_];
__device__ float g_o[BT_ * D_];

__device__ volatile unsigned g_bar_gen = 0;
__device__ unsigned g_bar_cnt = 0;

typedef unsigned long long u64;
typedef unsigned int u32;

static __device__ __forceinline__ u64 ffma2(u64 a, u64 b, u64 c) {
    u64 d; asm("fma.rn.f32x2 %0, %1, %2, %3;" : "=l"(d) : "l"(a), "l"(b), "l"(c));
    return d;
}
static __device__ __forceinline__ u64 pack2(float x, float y) {
    u64 d; asm("mov.b64 %0, {%1, %2};" : "=l"(d) : "f"(x), "f"(y));
    return d;
}
static __device__ __forceinline__ float2 unpack2(u64 d) {
    float2 r; asm("mov.b64 {%0, %1}, %2;" : "=f"(r.x), "=f"(r.y) : "l"(d));
    return r;
}
static __device__ __forceinline__ u32 h2u(__half2 h) {
    u32 u; __builtin_memcpy(&u, &h, 4); return u;
}
static __device__ __forceinline__ __half2 u2h(u32 u) {
    __half2 h; __builtin_memcpy(&h, &u, 4); return h;
}
static __device__ __forceinline__ __half2 hex2(__half2 h) {
    u32 u = h2u(h);
    asm("ex2.approx.f16x2 %0, %0;" : "+r"(u));
    return u2h(u);
}
static __device__ __forceinline__ __half2 mask2(int k, int r) {
    u32 m = (k + 1 <= r) ? 0x3C003C00u : ((k <= r) ? 0x00003C00u : 0u);
    return u2h(m);
}
static __device__ __forceinline__ void mma_qk_f16(float* d, const u32* a, u32 b) {
    asm("mma.sync.aligned.m16n8k8.row.col.f32.f16.f16.f32 "
        "{%0,%1,%2,%3}, {%4,%5}, {%6}, {%7,%8,%9,%10};"
        : "=f"(d[0]), "=f"(d[1]), "=f"(d[2]), "=f"(d[3])
        : "r"(a[0]), "r"(a[1]), "r"(b),
          "f"(0.f), "f"(0.f), "f"(0.f), "f"(0.f));
}
static __device__ __forceinline__ void mma_f16(float* d, const u32* a, const u32* b) {
    asm("mma.sync.aligned.m16n8k16.row.col.f32.f16.f16.f32 "
        "{%0,%1,%2,%3}, {%4,%5,%6,%7}, {%8,%9}, {%0,%1,%2,%3};"
        : "+f"(d[0]), "+f"(d[1]), "+f"(d[2]), "+f"(d[3])
        : "r"(a[0]), "r"(a[1]), "r"(a[2]), "r"(a[3]),
          "r"(b[0]), "r"(b[1]));
}

// generation-based grid barrier (all NBLK blocks must be resident)
static __device__ __forceinline__ void grid_barrier() {
    __syncthreads();
    if (threadIdx.x == 0) {
        __threadfence();
        unsigned gen = g_bar_gen;
        if (atomicAdd(&g_bar_cnt, 1u) == (unsigned)(NBLK - 1)) {
            g_bar_cnt = 0;
            __threadfence();
            g_bar_gen = gen + 1;
        } else {
            while (g_bar_gen == gen) { }
        }
        __threadfence();
    }
    __syncthreads();
}

// smem: 79360 bytes (phase-3 footprint is the max)
constexpr int SMEM_FLOATS = 9472 + 2 * 5184;
constexpr int SMEM_BYTES  = SMEM_FLOATS * 4;

static __device__ __forceinline__ void attn_dchunk(
    const u32* __restrict__ qf, u32 kb0, u32 kb1, const u32* __restrict__ vb,
    float* __restrict__ o, float& l0, float& l1,
    bool diag, int keybase, int r0, int tig2)
{
    float s0[4], s1[4];
    mma_qk_f16(s0, qf, kb0);
    mma_qk_f16(s1, qf, kb1);
    __half2 h0 = hex2(__floats2half2_rn(s0[0], s0[1]));
    __half2 h1 = hex2(__floats2half2_rn(s0[2], s0[3]));
    __half2 h2 = hex2(__floats2half2_rn(s1[0], s1[1]));
    __half2 h3 = hex2(__floats2half2_rn(s1[2], s1[3]));
    if (diag) {
        const int k0 = keybase + tig2;
        const int k1 = keybase + 8 + tig2;
        h0 = __hmul2(h0, mask2(k0, r0));
        h1 = __hmul2(h1, mask2(k0, r0 + 8));
        h2 = __hmul2(h2, mask2(k1, r0));
        h3 = __hmul2(h3, mask2(k1, r0 + 8));
    }
    {
        float2 f0 = __half22float2(__hadd2(h0, h2));
        l0 += f0.x + f0.y;
        float2 f1 = __half22float2(__hadd2(h1, h3));
        l1 += f1.x + f1.y;
    }
    u32 a[4] = { h2u(h0), h2u(h1), h2u(h2), h2u(h3) };
    mma_f16(o, a, vb);
}

__global__ __launch_bounds__(256, 2) void k_fused(
    float* __restrict__ out,
    const float* __restrict__ x,
    const float* __restrict__ Wq, const float* __restrict__ Wk,
    const float* __restrict__ Wv,
    const float* __restrict__ g1, const float* __restrict__ b1,
    const float* __restrict__ Wp, const float* __restrict__ bp,
    const float* __restrict__ W1, const float* __restrict__ b1v,
    const float* __restrict__ W2, const float* __restrict__ b2v,
    const float* __restrict__ g2, const float* __restrict__ bt2)
{
    extern __shared__ float sm[];
    const int tid  = threadIdx.x;
    const int bid  = blockIdx.x;
    const int half = tid >> 7;
    const int ht   = tid & 127;

    // =====================================================================
    // Phase 1: LN1 + QKV.  Half-block = one 32-token group (2 per block).
    // Results bounced through smem, stored coalesced (512B runs per warp).
    // =====================================================================
    {
        float* sh_w = sm;                          // [32][96]
        float* sh_h = sm + 3072 + half * 1056;     // [32][33] per half
        float* sOut = sm + 5184 + half * 3200;     // [32][100] per half

        // stage combined qkv weights (whole block)
        for (int i4 = tid; i4 < 768; i4 += 256) {
            int i = i4 * 4;
            int type = i >> 10, rem = i & 1023;
            int head = rem >> 8, d = (rem >> 3) & 31, kk = rem & 7;
            const float* W = (type == 0) ? Wq : (type == 1) ? Wk : Wv;
            *(float4*)&sh_w[d * 96 + type * 32 + head * 8 + kk] = *(const float4*)(W + rem);
        }
        __syncthreads();

        const int t0 = (bid * 2 + half) * 32;
        const int tk = ht >> 2, part = ht & 3;
        const int t  = t0 + tk;
        const int c0 = part * 8;
        const float4* xr = (const float4*)(x + t * 32 + c0);
        float4 v0 = xr[0], v1 = xr[1];
        float s  = v0.x + v0.y + v0.z + v0.w + v1.x + v1.y + v1.z + v1.w;
        float ss = v0.x*v0.x + v0.y*v0.y + v0.z*v0.z + v0.w*v0.w
                 + v1.x*v1.x + v1.y*v1.y + v1.z*v1.z + v1.w*v1.w;
        s  += __shfl_xor_sync(0xffffffffu, s, 1);
        ss += __shfl_xor_sync(0xffffffffu, ss, 1);
        s  += __shfl_xor_sync(0xffffffffu, s, 2);
        ss += __shfl_xor_sync(0xffffffffu, ss, 2);
        const float mu = s * 0.03125f;
        const float rs = rsqrtf(ss * 0.03125f - mu * mu + 1e-5f);
        float hv[8];
        {
            const float* vv = (const float*)&v0;
            #pragma unroll
            for (int i = 0; i < 4; i++)
                hv[i] = (vv[i] - mu) * rs * __ldg(g1 + c0 + i) + __ldg(b1 + c0 + i);
            const float* vw = (const float*)&v1;
            #pragma unroll
            for (int i = 0; i < 4; i++)
                hv[4 + i] = (vw[i] - mu) * rs * __ldg(g1 + c0 + 4 + i) + __ldg(b1 + c0 + 4 + i);
        }
        #pragma unroll
        for (int i = 0; i < 8; i++) sh_h[tk * 33 + c0 + i] = hv[i];
        float4* hr = (float4*)(g_h + t * 32 + c0);
        hr[0] = make_float4(hv[0], hv[1], hv[2], hv[3]);
        hr[1] = make_float4(hv[4], hv[5], hv[6], hv[7]);
        asm volatile("bar.sync %0, 128;" :: "r"(1 + half) : "memory");

        const int to = ht >> 3;
        const int oo = ht & 7;
        u64 acc0[6] = {0,0,0,0,0,0}, acc1[6] = {0,0,0,0,0,0};
        #pragma unroll 4
        for (int kd = 0; kd < 32; kd++) {
            float a0 = sh_h[2 * to * 33 + kd];
            float a1 = sh_h[(2 * to + 1) * 33 + kd];
            u64 ap0 = pack2(a0, a0), ap1 = pack2(a1, a1);
            const ulonglong2* wr = (const ulonglong2*)&sh_w[kd * 96 + oo * 12];
            ulonglong2 w0 = wr[0], w1 = wr[1], w2 = wr[2];
            u64 wv[6] = {w0.x, w0.y, w1.x, w1.y, w2.x, w2.y};
            #pragma unroll
            for (int i = 0; i < 6; i++) {
                acc0[i] = ffma2(ap0, wv[i], acc0[i]);
                acc1[i] = ffma2(ap1, wv[i], acc1[i]);
            }
        }
        // write accumulators into sOut (stride 100; float2-aligned offsets)
        #pragma unroll
        for (int i2 = 0; i2 < 6; i2++) {
            int o = oo * 12 + 2 * i2;
            float2 u0 = unpack2(acc0[i2]);
            float2 u1 = unpack2(acc1[i2]);
            *(float2*)&sOut[(2 * to)     * 100 + o] = u0;
            *(float2*)&sOut[(2 * to + 1) * 100 + o] = u1;
        }
        asm volatile("bar.sync %0, 128;" :: "r"(1 + half) : "memory");

        // coalesced bounce-out: 12 regions (type*4+head), 512B runs per warp
        const float QS = 0.51006973f;          // log2(e)/sqrt(8)
        const int b   = t0 >> 11;
        const int tl0 = t0 & 2047;
        #pragma unroll
        for (int r = 0; r < 6; r++) {
            int idx    = ht + 128 * r;         // 0..767
            int region = idx >> 6;             // 0..11 = type*4 + head
            int within = idx & 63;
            int token  = within >> 1;
            int kkh    = (within & 1) * 4;
            int type   = region >> 2, head = region & 3;
            float4 v = *(const float4*)&sOut[token * 100 + region * 8 + kkh];
            float* base = (type == 0) ? g_q : (type == 1) ? g_k : g_v;
            if (type == 0) { v.x *= QS; v.y *= QS; v.z *= QS; v.w *= QS; }
            *(float4*)(base + ((b * 4 + head) * 2048 + tl0 + token) * 8 + kkh) = v;
        }
    }

    grid_barrier();

    // =====================================================================
    // Phase 2: causal attention, balanced pairing (tiles j and 15-j).
    // =====================================================================
    {
        u32* su  = (u32*)sm;
        u32* sKh = su;           // [2][128*4]
        u32* sV  = su + 1024;    // [2][8*68]

        const int w   = tid >> 5;
        const int ln  = tid & 31;
        const int g   = ln >> 2;
        const int tig = ln & 3;
        const int bh  = bid & 31;
        const int j   = bid >> 5;          // 0..7
        const int jhi = 15 - j;

        const float* Qg = g_q + bh * T_ * 8;
        const int qa0 = j   * 128 + w * 16 + g;
        const int qb0 = jhi * 128 + w * 16 + g;

        u32 qaf[2], qbf[2];
        qaf[0] = h2u(__floats2half2_rn(Qg[(qa0)     * 8 + 2 * tig], Qg[(qa0)     * 8 + 2 * tig + 1]));
        qaf[1] = h2u(__floats2half2_rn(Qg[(qa0 + 8) * 8 + 2 * tig], Qg[(qa0 + 8) * 8 + 2 * tig + 1]));
        qbf[0] = h2u(__floats2half2_rn(Qg[(qb0)     * 8 + 2 * tig], Qg[(qb0)     * 8 + 2 * tig + 1]));
        qbf[1] = h2u(__floats2half2_rn(Qg[(qb0 + 8) * 8 + 2 * tig], Qg[(qb0 + 8) * 8 + 2 * tig + 1]));

        float oa[4] = {0.f, 0.f, 0.f, 0.f}, ob[4] = {0.f, 0.f, 0.f, 0.f};
        float la0 = 0.f, la1 = 0.f, lb0 = 0.f, lb1 = 0.f;

        const int srow  = tid >> 1;
        const int shalf = tid & 1;
        const float* Kr = g_k + (bh * T_ + srow) * 8 + shalf * 4;
        const float* Vr = g_v + (bh * T_ + srow) * 8 + shalf * 4;

        float4 kreg = *(const float4*)(Kr);
        float4 vreg = *(const float4*)(Vr);

        for (int kt = 0; kt <= jhi; kt++) {
            const int s0 = kt * 128;
            const int buf = kt & 1;
            {
                u32* kd = &sKh[buf * 512 + srow * 4 + shalf * 2];
                kd[0] = h2u(__floats2half2_rn(kreg.x, kreg.y));
                kd[1] = h2u(__floats2half2_rn(kreg.z, kreg.w));
                float px = __shfl_xor_sync(0xffffffffu, vreg.x, 2);
                float py = __shfl_xor_sync(0xffffffffu, vreg.y, 2);
                float pz = __shfl_xor_sync(0xffffffffu, vreg.z, 2);
                float pw = __shfl_xor_sync(0xffffffffu, vreg.w, 2);
                if ((tid & 2) == 0) {
                    int kp = tid >> 2;
                    int d0 = shalf * 4;
                    sV[buf * 544 + (d0 + 0) * 68 + kp] = h2u(__floats2half2_rn(vreg.x, px));
                    sV[buf * 544 + (d0 + 1) * 68 + kp] = h2u(__floats2half2_rn(vreg.y, py));
                    sV[buf * 544 + (d0 + 2) * 68 + kp] = h2u(__floats2half2_rn(vreg.z, pz));
                    sV[buf * 544 + (d0 + 3) * 68 + kp] = h2u(__floats2half2_rn(vreg.w, pw));
                }
            }
            __syncthreads();

            if (kt < jhi) {
                kreg = *(const float4*)(Kr + (kt + 1) * 128 * 8);
                vreg = *(const float4*)(Vr + (kt + 1) * 128 * 8);
            }

            const bool qaAct = (kt <= j);
            const bool dA = (kt == j), dB = (kt == jhi);

            #pragma unroll 2
            for (int c = 0; c < 8; c++) {
                u32 kb0 = sKh[buf * 512 + (16 * c + g) * 4 + tig];
                u32 kb1 = sKh[buf * 512 + (16 * c + 8 + g) * 4 + tig];
                u32 vb[2];
                vb[0] = sV[buf * 544 + g * 68 + 8 * c + tig];
                vb[1] = sV[buf * 544 + g * 68 + 8 * c + tig + 4];
                if (qaAct)
                    attn_dchunk(qaf, kb0, kb1, vb, oa, la0, la1, dA, s0 + 16 * c, qa0, 2 * tig);
                attn_dchunk(qbf, kb0, kb1, vb, ob, lb0, lb1, dB, s0 + 16 * c, qb0, 2 * tig);
            }
        }

        la0 += __shfl_xor_sync(0xffffffffu, la0, 1);
        la0 += __shfl_xor_sync(0xffffffffu, la0, 2);
        la1 += __shfl_xor_sync(0xffffffffu, la1, 1);
        la1 += __shfl_xor_sync(0xffffffffu, la1, 2);
        lb0 += __shfl_xor_sync(0xffffffffu, lb0, 1);
        lb0 += __shfl_xor_sync(0xffffffffu, lb0, 2);
        lb1 += __shfl_xor_sync(0xffffffffu, lb1, 1);
        lb1 += __shfl_xor_sync(0xffffffffu, lb1, 2);
        const float ra0 = __fdividef(1.f, la0);
        const float ra1 = __fdividef(1.f, la1);
        const float rb0 = __fdividef(1.f, lb0);
        const float rb1 = __fdividef(1.f, lb1);

        const int bb = bh >> 2, h = bh & 3;
        const int colo = h * 8 + 2 * tig;
        *(float2*)(g_o + (bb * T_ + qa0)     * 32 + colo) = make_float2(oa[0] * ra0, oa[1] * ra0);
        *(float2*)(g_o + (bb * T_ + qa0 + 8) * 32 + colo) = make_float2(oa[2] * ra1, oa[3] * ra1);
        *(float2*)(g_o + (bb * T_ + qb0)     * 32 + colo) = make_float2(ob[0] * rb0, ob[1] * rb0);
        *(float2*)(g_o + (bb * T_ + qb0 + 8) * 32 + colo) = make_float2(ob[2] * rb1, ob[3] * rb1);
    }

    grid_barrier();

    // =====================================================================
    // Phase 3: proj + residual + LN2 + FFN + residual.
    // Half-block = one 32-token tile (2 per block), weights shared.
    // =====================================================================
    {
        float* sWp = sm;                 // [32][32]
        float* sW1 = sWp + 1024;         // [32][128]
        float* sW2 = sW1 + 4096;         // [128][32]
        float* sB  = sW2 + 4096;         // biases
        float* sb1 = sB + 128;
        float* sX  = sb1 + 128 + half * 5184;   // [32][33]
        float* sHid = sX + 1056;                 // [32][129]

        // stage weights (whole block)
        *(float4*)&sWp[tid * 4] = *(const float4*)(Wp + tid * 4);
        for (int i4 = tid; i4 < 1024; i4 += 256)
            *(float4*)&sW1[i4 * 4] = *(const float4*)(W1 + i4 * 4);
        for (int i4 = tid; i4 < 1024; i4 += 256)
            *(float4*)&sW2[i4 * 4] = *(const float4*)(W2 + i4 * 4);
        if (tid < 32) { sB[tid] = bp[tid]; sB[32 + tid] = b2v[tid];
                        sB[64 + tid] = g2[tid]; sB[96 + tid] = bt2[tid]; }
        if (tid >= 128 && tid < 256) sb1[tid - 128] = b1v[tid - 128];
        __syncthreads();

        const int t0  = (bid * 2 + half) * 32;
        const int bar = 1 + half;

        #pragma unroll
        for (int r = 0; r < 2; r++) {
            int idx = ht + 128 * r;
            int row = idx >> 3, c4 = idx & 7;
            float4 v = ((const float4*)(g_o + (t0 + row) * 32))[c4];
            float* d = &sX[row * 33 + c4 * 4];
            d[0] = v.x; d[1] = v.y; d[2] = v.z; d[3] = v.w;
        }
        asm volatile("bar.sync %0, 128;" :: "r"(bar) : "memory");

        // ---- stage A: x1 = h + o@Wproj + bproj ; h2 = LN2(x1) ----
        const int tr = ht >> 2, q4 = ht & 3;   // token, col-quarter (8 cols)
        const int c0 = q4 * 8;
        const int gt = t0 + tr;
        u64 accp[4] = {0, 0, 0, 0};
        #pragma unroll 4
        for (int kd = 0; kd < 32; kd++) {
            float a = sX[tr * 33 + kd];
            u64 ap = pack2(a, a);
            const ulonglong2* wr = (const ulonglong2*)&sWp[kd * 32 + c0];
            ulonglong2 w0 = wr[0], w1 = wr[1];
            accp[0] = ffma2(ap, w0.x, accp[0]); accp[1] = ffma2(ap, w0.y, accp[1]);
            accp[2] = ffma2(ap, w1.x, accp[2]); accp[3] = ffma2(ap, w1.y, accp[3]);
        }
        float xv[8];
        {
            const float4* hp = (const float4*)(g_h + gt * 32 + c0);
            float4 h0 = hp[0], h1 = hp[1];
            float2 u0 = unpack2(accp[0]), u1 = unpack2(accp[1]);
            float2 u2 = unpack2(accp[2]), u3 = unpack2(accp[3]);
            xv[0] = h0.x + u0.x + sB[c0 + 0];
            xv[1] = h0.y + u0.y + sB[c0 + 1];
            xv[2] = h0.z + u1.x + sB[c0 + 2];
            xv[3] = h0.w + u1.y + sB[c0 + 3];
            xv[4] = h1.x + u2.x + sB[c0 + 4];
            xv[5] = h1.y + u2.y + sB[c0 + 5];
            xv[6] = h1.z + u3.x + sB[c0 + 6];
            xv[7] = h1.w + u3.y + sB[c0 + 7];
        }
        float s = 0.f, ss = 0.f;
        #pragma unroll
        for (int i = 0; i < 8; i++) { s += xv[i]; ss += xv[i] * xv[i]; }
        s  += __shfl_xor_sync(0xffffffffu, s, 1);
        ss += __shfl_xor_sync(0xffffffffu, ss, 1);
        s  += __shfl_xor_sync(0xffffffffu, s, 2);
        ss += __shfl_xor_sync(0xffffffffu, ss, 2);
        const float mu = s * 0.03125f;
        const float rs = rsqrtf(ss * 0.03125f - mu * mu + 1e-5f);
        float h2r[8];
        #pragma unroll
        for (int i = 0; i < 8; i++)
            h2r[i] = (xv[i] - mu) * rs * sB[64 + c0 + i] + sB[96 + c0 + i];

        asm volatile("bar.sync %0, 128;" :: "r"(bar) : "memory");
        #pragma unroll
        for (int i = 0; i < 8; i++) sX[tr * 33 + c0 + i] = h2r[i];
        asm volatile("bar.sync %0, 128;" :: "r"(bar) : "memory");

        // ---- stage B: hid = relu(h2 @ W1 + b1) ----
        const int ttb = ht >> 4;   // 0..7 -> 4 tokens each
        const int oo  = ht & 15;   // 8 outs each
        u64 accB[4][4];
        #pragma unroll
        for (int jj = 0; jj < 4; jj++)
            #pragma unroll
            for (int i = 0; i < 4; i++) accB[jj][i] = 0;
        #pragma unroll 4
        for (int k = 0; k < 32; k++) {
            u64 ap[4];
            #pragma unroll
            for (int jj = 0; jj < 4; jj++) {
                float a = sX[(ttb * 4 + jj) * 33 + k];
                ap[jj] = pack2(a, a);
            }
            const ulonglong2* wr = (const ulonglong2*)&sW1[k * 128 + oo * 8];
            ulonglong2 ww0 = wr[0], ww1 = wr[1];
            u64 wv[4] = {ww0.x, ww0.y, ww1.x, ww1.y};
            #pragma unroll
            for (int jj = 0; jj < 4; jj++)
                #pragma unroll
                for (int i = 0; i < 4; i++)
                    accB[jj][i] = ffma2(ap[jj], wv[i], accB[jj][i]);
        }
        #pragma unroll
        for (int jj = 0; jj < 4; jj++)
            #pragma unroll
            for (int i = 0; i < 4; i++) {
                float2 u = unpack2(accB[jj][i]);
                float* d = &sHid[(ttb * 4 + jj) * 129 + oo * 8 + 2 * i];
                d[0] = fmaxf(u.x + sb1[oo * 8 + 2 * i], 0.f);
                d[1] = fmaxf(u.y + sb1[oo * 8 + 2 * i + 1], 0.f);
            }
        asm volatile("bar.sync %0, 128;" :: "r"(bar) : "memory");

        // ---- stage C: out = h2 + hid @ W2 + b2 ----
        u64 accC[4] = {0, 0, 0, 0};
        #pragma unroll 4
        for (int k = 0; k < 128; k++) {
            float a = sHid[tr * 129 + k];
            u64 ap = pack2(a, a);
            const ulonglong2* wr = (const ulonglong2*)&sW2[k * 32 + c0];
            ulonglong2 w0 = wr[0], w1 = wr[1];
            accC[0] = ffma2(ap, w0.x, accC[0]); accC[1] = ffma2(ap, w0.y, accC[1]);
            accC[2] = ffma2(ap, w1.x, accC[2]); accC[3] = ffma2(ap, w1.y, accC[3]);
        }
        float2 u0 = unpack2(accC[0]), u1 = unpack2(accC[1]);
        float2 u2 = unpack2(accC[2]), u3 = unpack2(accC[3]);
        float4* op = (float4*)(out + gt * 32 + c0);
        op[0] = make_float4(h2r[0] + u0.x + sB[32 + c0 + 0],
                            h2r[1] + u0.y + sB[32 + c0 + 1],
                            h2r[2] + u1.x + sB[32 + c0 + 2],
                            h2r[3] + u1.y + sB[32 + c0 + 3]);
        op[1] = make_float4(h2r[4] + u2.x + sB[32 + c0 + 4],
                            h2r[5] + u2.y + sB[32 + c0 + 5],
                            h2r[6] + u3.x + sB[32 + c0 + 6],
                            h2r[7] + u3.y + sB[32 + c0 + 7]);
    }
}

// ---------------------------------------------------------------------------
extern "C" void kernel_launch(void* const* d_in, const int* in_sizes, int n_in,
                              void* d_out, int out_size)
{
    const float* x   = (const float*)d_in[0];
    const float* Wq  = (const float*)d_in[1];
    const float* Wk  = (const float*)d_in[2];
    const float* Wv  = (const float*)d_in[3];
    const float* Wp  = (const float*)d_in[4];
    const float* bp  = (const float*)d_in[5];
    const float* g1  = (const float*)d_in[6];
    const float* b1  = (const float*)d_in[7];
    const float* W1  = (const float*)d_in[8];
    const float* b1f = (const float*)d_in[9];
    const float* W2  = (const float*)d_in[10];
    const float* b2f = (const float*)d_in[11];
    const float* g2  = (const float*)d_in[12];
    const float* bt2 = (const float*)d_in[13];
    float* out = (float*)d_out;

    cudaFuncSetAttribute((const void*)k_fused,
                         cudaFuncAttributeMaxDynamicSharedMemorySize, SMEM_BYTES);

    k_fused<<<NBLK, 256, SMEM_BYTES>>>(out, x, Wq, Wk, Wv, g1, b1,
                                       Wp, bp, W1, b1f, W2, b2f, g2, bt2);
}